// round 12
// baseline (speedup 1.0000x reference)
#include <cuda_runtime.h>
#include <cuda_fp16.h>
#include <cstdint>

// Shapes: n=8, b=64, h=128, f=256, hs=64
#define N_SEQ 8
#define B_DIM 64
#define H_DIM 128
#define F_DIM 256
#define HS 64
#define M_TOTAL (N_SEQ * B_DIM * H_DIM)   // 65536 rows

// Pre-split fp16 hi/lo Q,K,V (Q pre-scaled by 1/16)
__device__ __half g_Qh[M_TOTAL * HS], g_Ql[M_TOTAL * HS];
__device__ __half g_Kh[M_TOTAL * HS], g_Kl[M_TOTAL * HS];
__device__ __half g_Vh[M_TOTAL * HS], g_Vl[M_TOTAL * HS];
// W transposed+split: [192 out-cols][256 k], fp16 hi/lo (L2-resident)
__device__ __half g_Wth[192 * 256], g_Wtl[192 * 256];

__device__ __forceinline__ void split2h(float x, __half& h, __half& l) {
    h = __float2half(x);
    l = __float2half(x - __half2float(h));
}

__device__ __forceinline__ uint32_t smem_u32(const void* p) {
    uint32_t a;
    asm("{ .reg .u64 t; cvta.to.shared.u64 t, %1; cvt.u32.u64 %0, t; }" : "=r"(a) : "l"(p));
    return a;
}

// fp16 mma, f32 accumulate
__device__ __forceinline__ void mma16816(float* c, const uint32_t* a,
                                         uint32_t b0, uint32_t b1) {
    asm volatile(
        "mma.sync.aligned.m16n8k16.row.col.f32.f16.f16.f32 "
        "{%0,%1,%2,%3},{%4,%5,%6,%7},{%8,%9},{%0,%1,%2,%3};"
        : "+f"(c[0]), "+f"(c[1]), "+f"(c[2]), "+f"(c[3])
        : "r"(a[0]), "r"(a[1]), "r"(a[2]), "r"(a[3]), "r"(b0), "r"(b1));
}
__device__ __forceinline__ void ldsm4(uint32_t& r0, uint32_t& r1, uint32_t& r2,
                                      uint32_t& r3, uint32_t addr) {
    asm volatile("ldmatrix.sync.aligned.m8n8.x4.shared.b16 {%0,%1,%2,%3}, [%4];"
                 : "=r"(r0), "=r"(r1), "=r"(r2), "=r"(r3) : "r"(addr));
}
__device__ __forceinline__ void ldsm4t(uint32_t& r0, uint32_t& r1, uint32_t& r2,
                                       uint32_t& r3, uint32_t addr) {
    asm volatile("ldmatrix.sync.aligned.m8n8.x4.trans.shared.b16 {%0,%1,%2,%3}, [%4];"
                 : "=r"(r0), "=r"(r1), "=r"(r2), "=r"(r3) : "r"(addr));
}

// ---------------------------------------------------------------------------
// Kernel W: one-time W transpose + fp16 hi/lo split. grid 192, block 256.
// ---------------------------------------------------------------------------
__global__ __launch_bounds__(256) void wsplit_kernel(
    const float* __restrict__ Wq,
    const float* __restrict__ Wk,
    const float* __restrict__ Wv)
{
    int idx = blockIdx.x * 256 + threadIdx.x;   // 0..49151
    int ng = idx >> 8;                          // 0..191
    int k  = idx & 255;
    const float* W = (ng < 64) ? Wq : (ng < 128) ? Wk : Wv;
    float v = W[(size_t)k * HS + (ng & 63)];
    __half h, l;
    split2h(v, h, l);
    g_Wth[ng * 256 + k] = h;
    g_Wtl[ng * 256 + k] = l;
}

// ---------------------------------------------------------------------------
// Kernel A: merged QKV GEMM via raw fp16 mma split-3.
// out(65536 x 192) = x(65536 x 256) @ Wt^T. grid 512, block 256 (8 warps).
// CTA: 128 rows x 192 cols; warp: 16 rows x 192 cols (24 acc frags).
// K chunks of 32 (2 k-steps). x read ONCE total. Q scale at epilogue.
// ---------------------------------------------------------------------------
#define QXS 40   // x tile stride (fp16)
#define QWS 40   // Wt tile stride (fp16)

__global__ __launch_bounds__(256) void qkv_kernel(const float* __restrict__ x)
{
    extern __shared__ __half qsm[];
    __half* xs_hi = qsm;                        // [128][40]
    __half* xs_lo = xs_hi + 128 * QXS;
    __half* wt_hi = xs_lo + 128 * QXS;          // [192][40]
    __half* wt_lo = wt_hi + 192 * QWS;

    const int t    = threadIdx.x;
    const int w    = t >> 5;
    const int lane = t & 31;
    const int g    = lane >> 2;
    const int tg   = lane & 3;
    const int rowBase = blockIdx.x * 128;

    const uint32_t xhb = smem_u32(xs_hi), xlb = smem_u32(xs_lo);
    const uint32_t whb = smem_u32(wt_hi), wlb = smem_u32(wt_lo);

    // lane-invariant ldmatrix offsets (bytes), stride 40 halves = 80 B
    const uint32_t aofs  = (uint32_t)(((lane & 15) * QXS + ((lane >> 4) << 3)) * 2);
    const uint32_t bofs  = (uint32_t)((((lane & 7) + ((lane >> 4) << 3)) * QWS
                                      + (((lane >> 3) & 1) << 3)) * 2);

    float acc[24][4];
#pragma unroll
    for (int nf = 0; nf < 24; nf++)
#pragma unroll
        for (int c = 0; c < 4; c++) acc[nf][c] = 0.f;

    for (int k0 = 0; k0 < F_DIM; k0 += 32) {
        // x tile 128x32 fp32 -> fp16 hi/lo (1024 float4 tasks, 4/thread)
#pragma unroll
        for (int p = 0; p < 4; p++) {
            int e = t + p * 256;
            int row = e >> 3;
            int lc  = (e & 7) * 4;
            float4 v = *(const float4*)&x[(size_t)(rowBase + row) * F_DIM + k0 + lc];
            __half h0,l0,h1,l1,h2,l2,h3,l3;
            split2h(v.x,h0,l0); split2h(v.y,h1,l1);
            split2h(v.z,h2,l2); split2h(v.w,h3,l3);
            *(__half2*)&xs_hi[row * QXS + lc]     = __halves2half2(h0, h1);
            *(__half2*)&xs_hi[row * QXS + lc + 2] = __halves2half2(h2, h3);
            *(__half2*)&xs_lo[row * QXS + lc]     = __halves2half2(l0, l1);
            *(__half2*)&xs_lo[row * QXS + lc + 2] = __halves2half2(l2, l3);
        }
        // Wt tiles 192x32 fp16 hi+lo (1536 uint4 tasks, 6/thread)
#pragma unroll
        for (int p = 0; p < 6; p++) {
            int e = t + p * 256;
            int arr = (e >= 768) ? 1 : 0;
            int idx = e - arr * 768;
            int row = idx >> 2;         // 0..191
            int ch  = idx & 3;          // 4 x uint4 per row (32 halves)
            const __half* src = arr ? g_Wtl : g_Wth;
            __half* dst = arr ? wt_lo : wt_hi;
            *(uint4*)&dst[row * QWS + ch * 8] =
                *(const uint4*)&src[row * 256 + k0 + ch * 8];
        }
        __syncthreads();

#pragma unroll
        for (int ks = 0; ks < 2; ks++) {
            uint32_t ah[4], al[4];
            uint32_t off = (uint32_t)((w * 16 * QXS + ks * 16) * 2);
            ldsm4(ah[0], ah[1], ah[2], ah[3], xhb + off + aofs);
            ldsm4(al[0], al[1], al[2], al[3], xlb + off + aofs);
#pragma unroll
            for (int nf2 = 0; nf2 < 12; nf2++) {
                uint32_t boff = (uint32_t)((nf2 * 16 * QWS + ks * 16) * 2);
                uint32_t bh0, bh1, bh2, bh3, bl0, bl1, bl2, bl3;
                ldsm4(bh0, bh1, bh2, bh3, whb + boff + bofs);
                ldsm4(bl0, bl1, bl2, bl3, wlb + boff + bofs);
                mma16816(acc[2 * nf2],     ah, bh0, bh1);
                mma16816(acc[2 * nf2],     al, bh0, bh1);
                mma16816(acc[2 * nf2],     ah, bl0, bl1);
                mma16816(acc[2 * nf2 + 1], ah, bh2, bh3);
                mma16816(acc[2 * nf2 + 1], al, bh2, bh3);
                mma16816(acc[2 * nf2 + 1], ah, bl2, bl3);
            }
        }
        __syncthreads();
    }

    // epilogue: split acc to fp16 hi/lo, route to Q/K/V (Q scaled by 1/16)
#pragma unroll
    for (int nf = 0; nf < 24; nf++) {
        int ncol = nf * 8;
        int m    = ncol >> 6;           // 0:Q 1:K 2:V
        int col  = (ncol & 63) + 2 * tg;
        float sc = (m == 0) ? 0.0625f : 1.0f;
        __half* __restrict__ outH = (m == 0) ? g_Qh : (m == 1) ? g_Kh : g_Vh;
        __half* __restrict__ outL = (m == 0) ? g_Ql : (m == 1) ? g_Kl : g_Vl;
        size_t r0 = (size_t)(rowBase + w * 16 + g) * HS + col;
        size_t r1 = (size_t)(rowBase + w * 16 + g + 8) * HS + col;
        __half h0,l0,h1,l1,h2,l2,h3,l3;
        split2h(acc[nf][0] * sc, h0, l0);
        split2h(acc[nf][1] * sc, h1, l1);
        split2h(acc[nf][2] * sc, h2, l2);
        split2h(acc[nf][3] * sc, h3, l3);
        *(__half2*)&outH[r0] = __halves2half2(h0, h1);
        *(__half2*)&outL[r0] = __halves2half2(l0, l1);
        *(__half2*)&outH[r1] = __halves2half2(h2, h3);
        *(__half2*)&outL[r1] = __halves2half2(l2, l3);
    }
}

// ---------------------------------------------------------------------------
// Kernel B: FA-style attention, fp16 mma f32-accum. Grid 512 = (j,b),
// block 256 (8 warps); warp owns 16 of 128 q rows. S split-3; PV single-pass.
// K hi/lo + V hi in smem stride 72; K/V tile copied ONCE per (j,b).
// ---------------------------------------------------------------------------
#define KVS 72

__global__ __launch_bounds__(256) void attn_kernel(float* __restrict__ out)
{
    extern __shared__ __half sm[];
    __half* kh = sm;
    __half* kl = kh + 128 * KVS;
    __half* vh = kl + 128 * KVS;

    const int t    = threadIdx.x;
    const int w    = t >> 5;
    const int lane = t & 31;
    const int g    = lane >> 2;
    const int tg   = lane & 3;
    const int j    = blockIdx.x & 7;
    const int b    = blockIdx.x >> 3;
    const int qrow = (j * B_DIM + b) * H_DIM;

    const uint32_t khb = smem_u32(kh), klb = smem_u32(kl);
    const uint32_t vhb = smem_u32(vh);

    const uint32_t aofs  = (uint32_t)(((lane & 15) * KVS + ((lane >> 4) << 3)) * 2);
    const uint32_t kmofs = (uint32_t)((((lane & 7) + ((lane >> 4) << 3)) * KVS
                                       + (((lane >> 3) & 1) << 3)) * 2);
    const uint32_t vmofs = (uint32_t)((((lane & 7) + (((lane >> 3) & 1) << 3)) * KVS
                                       + ((lane >> 4) << 3)) * 2);

    // ---- stage Q (128 rows) into kh/kl, hoist A-frags ----
#pragma unroll
    for (int p = 0; p < 8; p++) {
        int e = t + p * 256;            // 2048 uint4 tasks
        int arr = e >> 10;              // 0: hi, 1: lo
        int idx = e & 1023;
        int row = idx >> 3;
        int ch  = idx & 7;
        const __half* src = arr ? g_Ql : g_Qh;
        __half* dst = arr ? kl : kh;
        *(uint4*)&dst[row * KVS + ch * 8] =
            *(const uint4*)&src[(size_t)(qrow + row) * HS + ch * 8];
    }
    __syncthreads();

    uint32_t qhf[4][4], qlf[4][4];
#pragma unroll
    for (int ks = 0; ks < 4; ks++) {
        uint32_t off = (uint32_t)((w * 16 * KVS + ks * 16) * 2);
        ldsm4(qhf[ks][0], qhf[ks][1], qhf[ks][2], qhf[ks][3], khb + off + aofs);
        ldsm4(qlf[ks][0], qlf[ks][1], qlf[ks][2], qlf[ks][3], klb + off + aofs);
    }

    float oacc[8][4];
#pragma unroll
    for (int nf = 0; nf < 8; nf++)
#pragma unroll
        for (int c = 0; c < 4; c++) oacc[nf][c] = 0.f;

    for (int i = 0; i < N_SEQ; i++) {
        __syncthreads();   // prev PV reads done (and Q-frag loads at i==0)
        const int kb0 = (i * B_DIM + b) * H_DIM;
        // copy K hi/lo + V hi: 3072 uint4 tasks, 12/thread
#pragma unroll 6
        for (int p = 0; p < 12; p++) {
            int e = t + p * 256;
            int arr = e >> 10;          // 0..2
            int idx = e & 1023;
            int row = idx >> 3;
            int ch  = idx & 7;
            const __half* src = (arr == 0) ? g_Kh : (arr == 1) ? g_Kl : g_Vh;
            __half* dst = (arr == 0) ? kh : (arr == 1) ? kl : vh;
            *(uint4*)&dst[row * KVS + ch * 8] =
                *(const uint4*)&src[(size_t)(kb0 + row) * HS + ch * 8];
        }
        __syncthreads();

        // ---- S = Q K^T : split-3, 16 rows x 128 keys in registers ----
        float sacc[16][4];
#pragma unroll
        for (int nf = 0; nf < 16; nf++)
#pragma unroll
            for (int c = 0; c < 4; c++) sacc[nf][c] = 0.f;

#pragma unroll
        for (int ks = 0; ks < 4; ks++) {
#pragma unroll
            for (int nfp = 0; nfp < 8; nfp++) {
                uint32_t off = (uint32_t)((nfp * 16 * KVS + ks * 16) * 2);
                uint32_t bh0, bh1, bh2, bh3, bl0, bl1, bl2, bl3;
                ldsm4(bh0, bh1, bh2, bh3, khb + off + kmofs);
                ldsm4(bl0, bl1, bl2, bl3, klb + off + kmofs);
                mma16816(sacc[2 * nfp],     qhf[ks], bh0, bh1);
                mma16816(sacc[2 * nfp],     qlf[ks], bh0, bh1);
                mma16816(sacc[2 * nfp],     qhf[ks], bl0, bl1);
                mma16816(sacc[2 * nfp + 1], qhf[ks], bh2, bh3);
                mma16816(sacc[2 * nfp + 1], qlf[ks], bh2, bh3);
                mma16816(sacc[2 * nfp + 1], qhf[ks], bl2, bl3);
            }
        }

        // ---- softmax in registers (rows w*16+g and +8) ----
        float mx_a = sacc[0][0], mx_b = sacc[0][2];
#pragma unroll
        for (int nf = 0; nf < 16; nf++) {
            mx_a = fmaxf(mx_a, fmaxf(sacc[nf][0], sacc[nf][1]));
            mx_b = fmaxf(mx_b, fmaxf(sacc[nf][2], sacc[nf][3]));
        }
        mx_a = fmaxf(mx_a, __shfl_xor_sync(0xffffffffu, mx_a, 1));
        mx_a = fmaxf(mx_a, __shfl_xor_sync(0xffffffffu, mx_a, 2));
        mx_b = fmaxf(mx_b, __shfl_xor_sync(0xffffffffu, mx_b, 1));
        mx_b = fmaxf(mx_b, __shfl_xor_sync(0xffffffffu, mx_b, 2));
        float sum_a = 0.f, sum_b = 0.f;
#pragma unroll
        for (int nf = 0; nf < 16; nf++) {
            sacc[nf][0] = __expf(sacc[nf][0] - mx_a);
            sacc[nf][1] = __expf(sacc[nf][1] - mx_a);
            sacc[nf][2] = __expf(sacc[nf][2] - mx_b);
            sacc[nf][3] = __expf(sacc[nf][3] - mx_b);
            sum_a += sacc[nf][0] + sacc[nf][1];
            sum_b += sacc[nf][2] + sacc[nf][3];
        }
        sum_a += __shfl_xor_sync(0xffffffffu, sum_a, 1);
        sum_a += __shfl_xor_sync(0xffffffffu, sum_a, 2);
        sum_b += __shfl_xor_sync(0xffffffffu, sum_b, 1);
        sum_b += __shfl_xor_sync(0xffffffffu, sum_b, 2);
        const float inv_a = 1.0f / sum_a, inv_b = 1.0f / sum_b;

        // ---- pack P into A-fragments (fp16) ----
        uint32_t pah[8][4];
#pragma unroll
        for (int s = 0; s < 8; s++) {
#pragma unroll
            for (int hf = 0; hf < 2; hf++) {
                int nf = 2 * s + hf;
                __half2 p01 = __floats2half2_rn(sacc[nf][0] * inv_a,
                                                sacc[nf][1] * inv_a);
                __half2 p23 = __floats2half2_rn(sacc[nf][2] * inv_b,
                                                sacc[nf][3] * inv_b);
                pah[s][2 * hf]     = *(uint32_t*)&p01;
                pah[s][2 * hf + 1] = *(uint32_t*)&p23;
            }
        }

        // ---- O += P V : single pass, V via ldmatrix.trans ----
#pragma unroll
        for (int s = 0; s < 8; s++) {
#pragma unroll
            for (int nfp = 0; nfp < 4; nfp++) {
                uint32_t off = (uint32_t)((s * 16 * KVS + nfp * 16) * 2);
                uint32_t bh0, bh1, bh2, bh3;
                ldsm4t(bh0, bh1, bh2, bh3, vhb + off + vmofs);
                mma16816(oacc[2 * nfp],     pah[s], bh0, bh1);
                mma16816(oacc[2 * nfp + 1], pah[s], bh2, bh3);
            }
        }
    }

    // ---- write O ----
#pragma unroll
    for (int nf = 0; nf < 8; nf++) {
        size_t r0 = (size_t)(qrow + w * 16 + g) * HS + nf * 8 + 2 * tg;
        size_t r1 = (size_t)(qrow + w * 16 + g + 8) * HS + nf * 8 + 2 * tg;
        *(float2*)&out[r0] = make_float2(oacc[nf][0], oacc[nf][1]);
        *(float2*)&out[r1] = make_float2(oacc[nf][2], oacc[nf][3]);
    }
}

// ---------------------------------------------------------------------------
extern "C" void kernel_launch(void* const* d_in, const int* in_sizes, int n_in,
                              void* d_out, int out_size)
{
    const float* x  = (const float*)d_in[0];
    const float* Wq = (const float*)d_in[1];
    const float* Wk = (const float*)d_in[2];
    const float* Wv = (const float*)d_in[3];
    float* out = (float*)d_out;

    wsplit_kernel<<<192, 256>>>(Wq, Wk, Wv);

    int qsmemB = (2 * 128 * QXS + 2 * 192 * QWS) * (int)sizeof(__half);  // 51200
    cudaFuncSetAttribute(qkv_kernel, cudaFuncAttributeMaxDynamicSharedMemorySize, qsmemB);
    qkv_kernel<<<512, 256, qsmemB>>>(x);

    int asmemB = 3 * 128 * KVS * (int)sizeof(__half);   // 55296
    cudaFuncSetAttribute(attn_kernel, cudaFuncAttributeMaxDynamicSharedMemorySize, asmemB);
    attn_kernel<<<512, 256, asmemB>>>(out);
}

// round 13
// speedup vs baseline: 1.3225x; 1.3225x over previous
#include <cuda_runtime.h>
#include <cuda_fp16.h>
#include <cstdint>

// Shapes: n=8, b=64, h=128, f=256, hs=64
#define N_SEQ 8
#define B_DIM 64
#define H_DIM 128
#define F_DIM 256
#define HS 64
#define M_TOTAL (N_SEQ * B_DIM * H_DIM)   // 65536 rows

// fp16 Q,K,V (Q pre-scaled by 1/16). Projections computed split-3 (fp32-class)
// then rounded once to fp16 -> storage error u only.
__device__ __half g_Qh[M_TOTAL * HS];
__device__ __half g_Kh[M_TOTAL * HS];
__device__ __half g_Vh[M_TOTAL * HS];
// W transposed+split: [192 out-cols][256 k], fp16 hi/lo (L2-resident)
__device__ __half g_Wth[192 * 256], g_Wtl[192 * 256];

__device__ __forceinline__ void split2h(float x, __half& h, __half& l) {
    h = __float2half(x);
    l = __float2half(x - __half2float(h));
}

__device__ __forceinline__ uint32_t smem_u32(const void* p) {
    uint32_t a;
    asm("{ .reg .u64 t; cvta.to.shared.u64 t, %1; cvt.u32.u64 %0, t; }" : "=r"(a) : "l"(p));
    return a;
}

// fp16 mma, f32 accumulate
__device__ __forceinline__ void mma16816(float* c, const uint32_t* a,
                                         uint32_t b0, uint32_t b1) {
    asm volatile(
        "mma.sync.aligned.m16n8k16.row.col.f32.f16.f16.f32 "
        "{%0,%1,%2,%3},{%4,%5,%6,%7},{%8,%9},{%0,%1,%2,%3};"
        : "+f"(c[0]), "+f"(c[1]), "+f"(c[2]), "+f"(c[3])
        : "r"(a[0]), "r"(a[1]), "r"(a[2]), "r"(a[3]), "r"(b0), "r"(b1));
}
__device__ __forceinline__ void ldsm4(uint32_t& r0, uint32_t& r1, uint32_t& r2,
                                      uint32_t& r3, uint32_t addr) {
    asm volatile("ldmatrix.sync.aligned.m8n8.x4.shared.b16 {%0,%1,%2,%3}, [%4];"
                 : "=r"(r0), "=r"(r1), "=r"(r2), "=r"(r3) : "r"(addr));
}
__device__ __forceinline__ void ldsm4t(uint32_t& r0, uint32_t& r1, uint32_t& r2,
                                       uint32_t& r3, uint32_t addr) {
    asm volatile("ldmatrix.sync.aligned.m8n8.x4.trans.shared.b16 {%0,%1,%2,%3}, [%4];"
                 : "=r"(r0), "=r"(r1), "=r"(r2), "=r"(r3) : "r"(addr));
}

// ---------------------------------------------------------------------------
// Kernel W: one-time W transpose + fp16 hi/lo split. grid 192, block 256.
// ---------------------------------------------------------------------------
__global__ __launch_bounds__(256) void wsplit_kernel(
    const float* __restrict__ Wq,
    const float* __restrict__ Wk,
    const float* __restrict__ Wv)
{
    int idx = blockIdx.x * 256 + threadIdx.x;   // 0..49151
    int ng = idx >> 8;                          // 0..191
    int k  = idx & 255;
    const float* W = (ng < 64) ? Wq : (ng < 128) ? Wk : Wv;
    float v = W[(size_t)k * HS + (ng & 63)];
    __half h, l;
    split2h(v, h, l);
    g_Wth[ng * 256 + k] = h;
    g_Wtl[ng * 256 + k] = l;
}

// ---------------------------------------------------------------------------
// Kernel A: merged QKV GEMM via raw fp16 mma split-3 (projection accuracy),
// outputs rounded once to fp16. grid 512, block 256 (8 warps).
// CTA: 128 rows x 192 cols; warp: 16 rows x 192 cols (24 acc frags).
// ---------------------------------------------------------------------------
#define QXS 40
#define QWS 40

__global__ __launch_bounds__(256) void qkv_kernel(const float* __restrict__ x)
{
    extern __shared__ __half qsm[];
    __half* xs_hi = qsm;                        // [128][40]
    __half* xs_lo = xs_hi + 128 * QXS;
    __half* wt_hi = xs_lo + 128 * QXS;          // [192][40]
    __half* wt_lo = wt_hi + 192 * QWS;

    const int t    = threadIdx.x;
    const int w    = t >> 5;
    const int lane = t & 31;
    const int g    = lane >> 2;
    const int tg   = lane & 3;
    const int rowBase = blockIdx.x * 128;

    const uint32_t xhb = smem_u32(xs_hi), xlb = smem_u32(xs_lo);
    const uint32_t whb = smem_u32(wt_hi), wlb = smem_u32(wt_lo);

    const uint32_t aofs  = (uint32_t)(((lane & 15) * QXS + ((lane >> 4) << 3)) * 2);
    const uint32_t bofs  = (uint32_t)((((lane & 7) + ((lane >> 4) << 3)) * QWS
                                      + (((lane >> 3) & 1) << 3)) * 2);

    float acc[24][4];
#pragma unroll
    for (int nf = 0; nf < 24; nf++)
#pragma unroll
        for (int c = 0; c < 4; c++) acc[nf][c] = 0.f;

    for (int k0 = 0; k0 < F_DIM; k0 += 32) {
#pragma unroll
        for (int p = 0; p < 4; p++) {   // x tile 128x32 -> hi/lo
            int e = t + p * 256;
            int row = e >> 3;
            int lc  = (e & 7) * 4;
            float4 v = *(const float4*)&x[(size_t)(rowBase + row) * F_DIM + k0 + lc];
            __half h0,l0,h1,l1,h2,l2,h3,l3;
            split2h(v.x,h0,l0); split2h(v.y,h1,l1);
            split2h(v.z,h2,l2); split2h(v.w,h3,l3);
            *(__half2*)&xs_hi[row * QXS + lc]     = __halves2half2(h0, h1);
            *(__half2*)&xs_hi[row * QXS + lc + 2] = __halves2half2(h2, h3);
            *(__half2*)&xs_lo[row * QXS + lc]     = __halves2half2(l0, l1);
            *(__half2*)&xs_lo[row * QXS + lc + 2] = __halves2half2(l2, l3);
        }
#pragma unroll
        for (int p = 0; p < 6; p++) {   // Wt tiles 192x32 hi+lo
            int e = t + p * 256;
            int arr = (e >= 768) ? 1 : 0;
            int idx = e - arr * 768;
            int row = idx >> 2;
            int ch  = idx & 3;
            const __half* src = arr ? g_Wtl : g_Wth;
            __half* dst = arr ? wt_lo : wt_hi;
            *(uint4*)&dst[row * QWS + ch * 8] =
                *(const uint4*)&src[row * 256 + k0 + ch * 8];
        }
        __syncthreads();

#pragma unroll
        for (int ks = 0; ks < 2; ks++) {
            uint32_t ah[4], al[4];
            uint32_t off = (uint32_t)((w * 16 * QXS + ks * 16) * 2);
            ldsm4(ah[0], ah[1], ah[2], ah[3], xhb + off + aofs);
            ldsm4(al[0], al[1], al[2], al[3], xlb + off + aofs);
#pragma unroll
            for (int nf2 = 0; nf2 < 12; nf2++) {
                uint32_t boff = (uint32_t)((nf2 * 16 * QWS + ks * 16) * 2);
                uint32_t bh0, bh1, bh2, bh3, bl0, bl1, bl2, bl3;
                ldsm4(bh0, bh1, bh2, bh3, whb + boff + bofs);
                ldsm4(bl0, bl1, bl2, bl3, wlb + boff + bofs);
                mma16816(acc[2 * nf2],     ah, bh0, bh1);
                mma16816(acc[2 * nf2],     al, bh0, bh1);
                mma16816(acc[2 * nf2],     ah, bl0, bl1);
                mma16816(acc[2 * nf2 + 1], ah, bh2, bh3);
                mma16816(acc[2 * nf2 + 1], al, bh2, bh3);
                mma16816(acc[2 * nf2 + 1], ah, bl2, bl3);
            }
        }
        __syncthreads();
    }

    // epilogue: round to fp16 once; route to Q/K/V (Q scaled by 1/16)
#pragma unroll
    for (int nf = 0; nf < 24; nf++) {
        int ncol = nf * 8;
        int m    = ncol >> 6;           // 0:Q 1:K 2:V
        int col  = (ncol & 63) + 2 * tg;
        float sc = (m == 0) ? 0.0625f : 1.0f;
        __half* __restrict__ outH = (m == 0) ? g_Qh : (m == 1) ? g_Kh : g_Vh;
        size_t r0 = (size_t)(rowBase + w * 16 + g) * HS + col;
        size_t r1 = (size_t)(rowBase + w * 16 + g + 8) * HS + col;
        *(__half2*)&outH[r0] = __floats2half2_rn(acc[nf][0] * sc, acc[nf][1] * sc);
        *(__half2*)&outH[r1] = __floats2half2_rn(acc[nf][2] * sc, acc[nf][3] * sc);
    }
}

// ---------------------------------------------------------------------------
// Kernel B: FA-style attention, fp16 mma f32-accum, SINGLE-PASS S and PV.
// grid 1024 = (j,b,half), block 128 (4 warps); warp owns 16 of 64 q rows.
// K + V tiles in smem stride 72; only hi precision throughout attention.
// ---------------------------------------------------------------------------
#define KVS 72

__global__ __launch_bounds__(128) void attn_kernel(float* __restrict__ out)
{
    extern __shared__ __half sm[];
    __half* kh = sm;
    __half* vh = kh + 128 * KVS;

    const int t    = threadIdx.x;
    const int w    = t >> 5;
    const int lane = t & 31;
    const int g    = lane >> 2;
    const int tg   = lane & 3;
    const int j    = blockIdx.x & 7;
    const int b    = (blockIdx.x >> 3) & 63;
    const int half_ = blockIdx.x >> 9;
    const int qrow = (j * B_DIM + b) * H_DIM + half_ * 64;

    const uint32_t khb = smem_u32(kh);
    const uint32_t vhb = smem_u32(vh);

    const uint32_t aofs  = (uint32_t)(((lane & 15) * KVS + ((lane >> 4) << 3)) * 2);
    const uint32_t kmofs = (uint32_t)((((lane & 7) + ((lane >> 4) << 3)) * KVS
                                       + (((lane >> 3) & 1) << 3)) * 2);
    const uint32_t vmofs = (uint32_t)((((lane & 7) + (((lane >> 3) & 1) << 3)) * KVS
                                       + ((lane >> 4) << 3)) * 2);

    // ---- stage Q (64 rows) into kh, hoist A-frags ----
#pragma unroll
    for (int p = 0; p < 4; p++) {
        int e = t + p * 128;            // 512 uint4 tasks
        int row = e >> 3;
        int ch  = e & 7;
        *(uint4*)&kh[row * KVS + ch * 8] =
            *(const uint4*)&g_Qh[(size_t)(qrow + row) * HS + ch * 8];
    }
    __syncthreads();

    uint32_t qhf[4][4];
#pragma unroll
    for (int ks = 0; ks < 4; ks++) {
        uint32_t off = (uint32_t)((w * 16 * KVS + ks * 16) * 2);
        ldsm4(qhf[ks][0], qhf[ks][1], qhf[ks][2], qhf[ks][3], khb + off + aofs);
    }

    float oacc[8][4];
#pragma unroll
    for (int nf = 0; nf < 8; nf++)
#pragma unroll
        for (int c = 0; c < 4; c++) oacc[nf][c] = 0.f;

    for (int i = 0; i < N_SEQ; i++) {
        __syncthreads();   // prev PV reads done (and Q-frag loads at i==0)
        const int kb0 = (i * B_DIM + b) * H_DIM;
        // copy K + V: 2048 uint4 tasks, 16/thread
#pragma unroll 8
        for (int p = 0; p < 16; p++) {
            int e = t + p * 128;
            int arr = e >> 10;          // 0: K, 1: V
            int idx = e & 1023;
            int row = idx >> 3;
            int ch  = idx & 7;
            const __half* src = arr ? g_Vh : g_Kh;
            __half* dst = arr ? vh : kh;
            *(uint4*)&dst[row * KVS + ch * 8] =
                *(const uint4*)&src[(size_t)(kb0 + row) * HS + ch * 8];
        }
        __syncthreads();

        // ---- S = Q K^T : SINGLE PASS, 16 rows x 128 keys in registers ----
        float sacc[16][4];
#pragma unroll
        for (int nf = 0; nf < 16; nf++)
#pragma unroll
            for (int c = 0; c < 4; c++) sacc[nf][c] = 0.f;

#pragma unroll
        for (int ks = 0; ks < 4; ks++) {
#pragma unroll
            for (int nfp = 0; nfp < 8; nfp++) {
                uint32_t off = (uint32_t)((nfp * 16 * KVS + ks * 16) * 2);
                uint32_t bh0, bh1, bh2, bh3;
                ldsm4(bh0, bh1, bh2, bh3, khb + off + kmofs);
                mma16816(sacc[2 * nfp],     qhf[ks], bh0, bh1);
                mma16816(sacc[2 * nfp + 1], qhf[ks], bh2, bh3);
            }
        }

        // ---- softmax in registers (rows g and g+8 of this warp's 16) ----
        float mx_a = sacc[0][0], mx_b = sacc[0][2];
#pragma unroll
        for (int nf = 0; nf < 16; nf++) {
            mx_a = fmaxf(mx_a, fmaxf(sacc[nf][0], sacc[nf][1]));
            mx_b = fmaxf(mx_b, fmaxf(sacc[nf][2], sacc[nf][3]));
        }
        mx_a = fmaxf(mx_a, __shfl_xor_sync(0xffffffffu, mx_a, 1));
        mx_a = fmaxf(mx_a, __shfl_xor_sync(0xffffffffu, mx_a, 2));
        mx_b = fmaxf(mx_b, __shfl_xor_sync(0xffffffffu, mx_b, 1));
        mx_b = fmaxf(mx_b, __shfl_xor_sync(0xffffffffu, mx_b, 2));
        float sum_a = 0.f, sum_b = 0.f;
#pragma unroll
        for (int nf = 0; nf < 16; nf++) {
            sacc[nf][0] = __expf(sacc[nf][0] - mx_a);
            sacc[nf][1] = __expf(sacc[nf][1] - mx_a);
            sacc[nf][2] = __expf(sacc[nf][2] - mx_b);
            sacc[nf][3] = __expf(sacc[nf][3] - mx_b);
            sum_a += sacc[nf][0] + sacc[nf][1];
            sum_b += sacc[nf][2] + sacc[nf][3];
        }
        sum_a += __shfl_xor_sync(0xffffffffu, sum_a, 1);
        sum_a += __shfl_xor_sync(0xffffffffu, sum_a, 2);
        sum_b += __shfl_xor_sync(0xffffffffu, sum_b, 1);
        sum_b += __shfl_xor_sync(0xffffffffu, sum_b, 2);
        const float inv_a = 1.0f / sum_a, inv_b = 1.0f / sum_b;

        // ---- pack P into A-fragments (fp16) ----
        uint32_t pah[8][4];
#pragma unroll
        for (int s = 0; s < 8; s++) {
#pragma unroll
            for (int hf = 0; hf < 2; hf++) {
                int nf = 2 * s + hf;
                __half2 p01 = __floats2half2_rn(sacc[nf][0] * inv_a,
                                                sacc[nf][1] * inv_a);
                __half2 p23 = __floats2half2_rn(sacc[nf][2] * inv_b,
                                                sacc[nf][3] * inv_b);
                pah[s][2 * hf]     = *(uint32_t*)&p01;
                pah[s][2 * hf + 1] = *(uint32_t*)&p23;
            }
        }

        // ---- O += P V : single pass, V via ldmatrix.trans ----
#pragma unroll
        for (int s = 0; s < 8; s++) {
#pragma unroll
            for (int nfp = 0; nfp < 4; nfp++) {
                uint32_t off = (uint32_t)((s * 16 * KVS + nfp * 16) * 2);
                uint32_t bh0, bh1, bh2, bh3;
                ldsm4t(bh0, bh1, bh2, bh3, vhb + off + vmofs);
                mma16816(oacc[2 * nfp],     pah[s], bh0, bh1);
                mma16816(oacc[2 * nfp + 1], pah[s], bh2, bh3);
            }
        }
    }

    // ---- write O ----
#pragma unroll
    for (int nf = 0; nf < 8; nf++) {
        size_t r0 = (size_t)(qrow + w * 16 + g) * HS + nf * 8 + 2 * tg;
        size_t r1 = (size_t)(qrow + w * 16 + g + 8) * HS + nf * 8 + 2 * tg;
        *(float2*)&out[r0] = make_float2(oacc[nf][0], oacc[nf][1]);
        *(float2*)&out[r1] = make_float2(oacc[nf][2], oacc[nf][3]);
    }
}

// ---------------------------------------------------------------------------
extern "C" void kernel_launch(void* const* d_in, const int* in_sizes, int n_in,
                              void* d_out, int out_size)
{
    const float* x  = (const float*)d_in[0];
    const float* Wq = (const float*)d_in[1];
    const float* Wk = (const float*)d_in[2];
    const float* Wv = (const float*)d_in[3];
    float* out = (float*)d_out;

    wsplit_kernel<<<192, 256>>>(Wq, Wk, Wv);

    int qsmemB = (2 * 128 * QXS + 2 * 192 * QWS) * (int)sizeof(__half);  // 51200
    cudaFuncSetAttribute(qkv_kernel, cudaFuncAttributeMaxDynamicSharedMemorySize, qsmemB);
    qkv_kernel<<<512, 256, qsmemB>>>(x);

    int asmemB = 2 * 128 * KVS * (int)sizeof(__half);   // 36864
    cudaFuncSetAttribute(attn_kernel, cudaFuncAttributeMaxDynamicSharedMemorySize, asmemB);
    attn_kernel<<<1024, 128, asmemB>>>(out);
}

// round 14
// speedup vs baseline: 1.7220x; 1.3021x over previous
#include <cuda_runtime.h>
#include <cuda_fp16.h>
#include <cstdint>

// Shapes: n=8, b=64, h=128, f=256, hs=64
#define N_SEQ 8
#define B_DIM 64
#define H_DIM 128
#define F_DIM 256
#define HS 64
#define M_TOTAL (N_SEQ * B_DIM * H_DIM)   // 65536 rows

// fp16 Q,K,V (Q pre-scaled by 1/16). Projections computed split-2
// (x_hi * [W_hi + W_lo], fp32 accum) then rounded once to fp16.
__device__ __half g_Qh[M_TOTAL * HS];
__device__ __half g_Kh[M_TOTAL * HS];
__device__ __half g_Vh[M_TOTAL * HS];
// W transposed+split: [192 out-cols][256 k], fp16 hi/lo (L2-resident)
__device__ __half g_Wth[192 * 256], g_Wtl[192 * 256];

__device__ __forceinline__ void split2h(float x, __half& h, __half& l) {
    h = __float2half(x);
    l = __float2half(x - __half2float(h));
}

__device__ __forceinline__ uint32_t smem_u32(const void* p) {
    uint32_t a;
    asm("{ .reg .u64 t; cvta.to.shared.u64 t, %1; cvt.u32.u64 %0, t; }" : "=r"(a) : "l"(p));
    return a;
}

// fp16 mma, f32 accumulate
__device__ __forceinline__ void mma16816(float* c, const uint32_t* a,
                                         uint32_t b0, uint32_t b1) {
    asm volatile(
        "mma.sync.aligned.m16n8k16.row.col.f32.f16.f16.f32 "
        "{%0,%1,%2,%3},{%4,%5,%6,%7},{%8,%9},{%0,%1,%2,%3};"
        : "+f"(c[0]), "+f"(c[1]), "+f"(c[2]), "+f"(c[3])
        : "r"(a[0]), "r"(a[1]), "r"(a[2]), "r"(a[3]), "r"(b0), "r"(b1));
}
__device__ __forceinline__ void ldsm4(uint32_t& r0, uint32_t& r1, uint32_t& r2,
                                      uint32_t& r3, uint32_t addr) {
    asm volatile("ldmatrix.sync.aligned.m8n8.x4.shared.b16 {%0,%1,%2,%3}, [%4];"
                 : "=r"(r0), "=r"(r1), "=r"(r2), "=r"(r3) : "r"(addr));
}
__device__ __forceinline__ void ldsm4t(uint32_t& r0, uint32_t& r1, uint32_t& r2,
                                       uint32_t& r3, uint32_t addr) {
    asm volatile("ldmatrix.sync.aligned.m8n8.x4.trans.shared.b16 {%0,%1,%2,%3}, [%4];"
                 : "=r"(r0), "=r"(r1), "=r"(r2), "=r"(r3) : "r"(addr));
}

// ---------------------------------------------------------------------------
// Kernel W: one-time W transpose + fp16 hi/lo split. grid 192, block 256.
// ---------------------------------------------------------------------------
__global__ __launch_bounds__(256) void wsplit_kernel(
    const float* __restrict__ Wq,
    const float* __restrict__ Wk,
    const float* __restrict__ Wv)
{
    int idx = blockIdx.x * 256 + threadIdx.x;   // 0..49151
    int ng = idx >> 8;                          // 0..191
    int k  = idx & 255;
    const float* W = (ng < 64) ? Wq : (ng < 128) ? Wk : Wv;
    float v = W[(size_t)k * HS + (ng & 63)];
    __half h, l;
    split2h(v, h, l);
    g_Wth[ng * 256 + k] = h;
    g_Wtl[ng * 256 + k] = l;
}

// ---------------------------------------------------------------------------
// Kernel A: merged QKV GEMM, split-2 (x hi-only; W hi/lo).
// grid 512, block 256 (8 warps). CTA: 128 rows x 192 cols.
// Warp: 16 rows x 192 cols (24 acc frags). K chunks of 32 (2 k-steps).
// ---------------------------------------------------------------------------
#define QXS 40
#define QWS 40

__global__ __launch_bounds__(256) void qkv_kernel(const float* __restrict__ x)
{
    extern __shared__ __half qsm[];
    __half* xs_hi = qsm;                        // [128][40]
    __half* wt_hi = xs_hi + 128 * QXS;          // [192][40]
    __half* wt_lo = wt_hi + 192 * QWS;

    const int t    = threadIdx.x;
    const int w    = t >> 5;
    const int lane = t & 31;
    const int g    = lane >> 2;
    const int tg   = lane & 3;
    const int rowBase = blockIdx.x * 128;

    const uint32_t xhb = smem_u32(xs_hi);
    const uint32_t whb = smem_u32(wt_hi), wlb = smem_u32(wt_lo);

    const uint32_t aofs  = (uint32_t)(((lane & 15) * QXS + ((lane >> 4) << 3)) * 2);
    const uint32_t bofs  = (uint32_t)((((lane & 7) + ((lane >> 4) << 3)) * QWS
                                      + (((lane >> 3) & 1) << 3)) * 2);

    float acc[24][4];
#pragma unroll
    for (int nf = 0; nf < 24; nf++)
#pragma unroll
        for (int c = 0; c < 4; c++) acc[nf][c] = 0.f;

    for (int k0 = 0; k0 < F_DIM; k0 += 32) {
#pragma unroll
        for (int p = 0; p < 4; p++) {   // x tile 128x32 -> fp16 hi only
            int e = t + p * 256;
            int row = e >> 3;
            int lc  = (e & 7) * 4;
            float4 v = *(const float4*)&x[(size_t)(rowBase + row) * F_DIM + k0 + lc];
            *(__half2*)&xs_hi[row * QXS + lc]     = __floats2half2_rn(v.x, v.y);
            *(__half2*)&xs_hi[row * QXS + lc + 2] = __floats2half2_rn(v.z, v.w);
        }
#pragma unroll
        for (int p = 0; p < 6; p++) {   // Wt tiles 192x32 hi+lo
            int e = t + p * 256;
            int arr = (e >= 768) ? 1 : 0;
            int idx = e - arr * 768;
            int row = idx >> 2;
            int ch  = idx & 3;
            const __half* src = arr ? g_Wtl : g_Wth;
            __half* dst = arr ? wt_lo : wt_hi;
            *(uint4*)&dst[row * QWS + ch * 8] =
                *(const uint4*)&src[row * 256 + k0 + ch * 8];
        }
        __syncthreads();

#pragma unroll
        for (int ks = 0; ks < 2; ks++) {
            uint32_t ah[4];
            uint32_t off = (uint32_t)((w * 16 * QXS + ks * 16) * 2);
            ldsm4(ah[0], ah[1], ah[2], ah[3], xhb + off + aofs);
#pragma unroll
            for (int nf2 = 0; nf2 < 12; nf2++) {
                uint32_t boff = (uint32_t)((nf2 * 16 * QWS + ks * 16) * 2);
                uint32_t bh0, bh1, bh2, bh3, bl0, bl1, bl2, bl3;
                ldsm4(bh0, bh1, bh2, bh3, whb + boff + bofs);
                ldsm4(bl0, bl1, bl2, bl3, wlb + boff + bofs);
                mma16816(acc[2 * nf2],     ah, bh0, bh1);
                mma16816(acc[2 * nf2],     ah, bl0, bl1);
                mma16816(acc[2 * nf2 + 1], ah, bh2, bh3);
                mma16816(acc[2 * nf2 + 1], ah, bl2, bl3);
            }
        }
        __syncthreads();
    }

    // epilogue: round to fp16 once; route to Q/K/V (Q scaled by 1/16)
#pragma unroll
    for (int nf = 0; nf < 24; nf++) {
        int ncol = nf * 8;
        int m    = ncol >> 6;           // 0:Q 1:K 2:V
        int col  = (ncol & 63) + 2 * tg;
        float sc = (m == 0) ? 0.0625f : 1.0f;
        __half* __restrict__ outH = (m == 0) ? g_Qh : (m == 1) ? g_Kh : g_Vh;
        size_t r0 = (size_t)(rowBase + w * 16 + g) * HS + col;
        size_t r1 = (size_t)(rowBase + w * 16 + g + 8) * HS + col;
        *(__half2*)&outH[r0] = __floats2half2_rn(acc[nf][0] * sc, acc[nf][1] * sc);
        *(__half2*)&outH[r1] = __floats2half2_rn(acc[nf][2] * sc, acc[nf][3] * sc);
    }
}

// ---------------------------------------------------------------------------
// Kernel B: FA-style attention, fp16 mma f32-accum, SINGLE-PASS S and PV.
// grid 1024 = (j,b,half), block 128 (4 warps); warp owns 16 of 64 q rows.
// K + V tiles in smem stride 72. (unchanged from R13)
// ---------------------------------------------------------------------------
#define KVS 72

__global__ __launch_bounds__(128) void attn_kernel(float* __restrict__ out)
{
    extern __shared__ __half sm[];
    __half* kh = sm;
    __half* vh = kh + 128 * KVS;

    const int t    = threadIdx.x;
    const int w    = t >> 5;
    const int lane = t & 31;
    const int g    = lane >> 2;
    const int tg   = lane & 3;
    const int j    = blockIdx.x & 7;
    const int b    = (blockIdx.x >> 3) & 63;
    const int half_ = blockIdx.x >> 9;
    const int qrow = (j * B_DIM + b) * H_DIM + half_ * 64;

    const uint32_t khb = smem_u32(kh);
    const uint32_t vhb = smem_u32(vh);

    const uint32_t aofs  = (uint32_t)(((lane & 15) * KVS + ((lane >> 4) << 3)) * 2);
    const uint32_t kmofs = (uint32_t)((((lane & 7) + ((lane >> 4) << 3)) * KVS
                                       + (((lane >> 3) & 1) << 3)) * 2);
    const uint32_t vmofs = (uint32_t)((((lane & 7) + (((lane >> 3) & 1) << 3)) * KVS
                                       + ((lane >> 4) << 3)) * 2);

    // ---- stage Q (64 rows) into kh, hoist A-frags ----
#pragma unroll
    for (int p = 0; p < 4; p++) {
        int e = t + p * 128;            // 512 uint4 tasks
        int row = e >> 3;
        int ch  = e & 7;
        *(uint4*)&kh[row * KVS + ch * 8] =
            *(const uint4*)&g_Qh[(size_t)(qrow + row) * HS + ch * 8];
    }
    __syncthreads();

    uint32_t qhf[4][4];
#pragma unroll
    for (int ks = 0; ks < 4; ks++) {
        uint32_t off = (uint32_t)((w * 16 * KVS + ks * 16) * 2);
        ldsm4(qhf[ks][0], qhf[ks][1], qhf[ks][2], qhf[ks][3], khb + off + aofs);
    }

    float oacc[8][4];
#pragma unroll
    for (int nf = 0; nf < 8; nf++)
#pragma unroll
        for (int c = 0; c < 4; c++) oacc[nf][c] = 0.f;

    for (int i = 0; i < N_SEQ; i++) {
        __syncthreads();   // prev PV reads done (and Q-frag loads at i==0)
        const int kb0 = (i * B_DIM + b) * H_DIM;
        // copy K + V: 2048 uint4 tasks, 16/thread
#pragma unroll 8
        for (int p = 0; p < 16; p++) {
            int e = t + p * 128;
            int arr = e >> 10;          // 0: K, 1: V
            int idx = e & 1023;
            int row = idx >> 3;
            int ch  = idx & 7;
            const __half* src = arr ? g_Vh : g_Kh;
            __half* dst = arr ? vh : kh;
            *(uint4*)&dst[row * KVS + ch * 8] =
                *(const uint4*)&src[(size_t)(kb0 + row) * HS + ch * 8];
        }
        __syncthreads();

        // ---- S = Q K^T : single pass, 16 rows x 128 keys in registers ----
        float sacc[16][4];
#pragma unroll
        for (int nf = 0; nf < 16; nf++)
#pragma unroll
            for (int c = 0; c < 4; c++) sacc[nf][c] = 0.f;

#pragma unroll
        for (int ks = 0; ks < 4; ks++) {
#pragma unroll
            for (int nfp = 0; nfp < 8; nfp++) {
                uint32_t off = (uint32_t)((nfp * 16 * KVS + ks * 16) * 2);
                uint32_t bh0, bh1, bh2, bh3;
                ldsm4(bh0, bh1, bh2, bh3, khb + off + kmofs);
                mma16816(sacc[2 * nfp],     qhf[ks], bh0, bh1);
                mma16816(sacc[2 * nfp + 1], qhf[ks], bh2, bh3);
            }
        }

        // ---- softmax in registers (rows g and g+8 of this warp's 16) ----
        float mx_a = sacc[0][0], mx_b = sacc[0][2];
#pragma unroll
        for (int nf = 0; nf < 16; nf++) {
            mx_a = fmaxf(mx_a, fmaxf(sacc[nf][0], sacc[nf][1]));
            mx_b = fmaxf(mx_b, fmaxf(sacc[nf][2], sacc[nf][3]));
        }
        mx_a = fmaxf(mx_a, __shfl_xor_sync(0xffffffffu, mx_a, 1));
        mx_a = fmaxf(mx_a, __shfl_xor_sync(0xffffffffu, mx_a, 2));
        mx_b = fmaxf(mx_b, __shfl_xor_sync(0xffffffffu, mx_b, 1));
        mx_b = fmaxf(mx_b, __shfl_xor_sync(0xffffffffu, mx_b, 2));
        float sum_a = 0.f, sum_b = 0.f;
#pragma unroll
        for (int nf = 0; nf < 16; nf++) {
            sacc[nf][0] = __expf(sacc[nf][0] - mx_a);
            sacc[nf][1] = __expf(sacc[nf][1] - mx_a);
            sacc[nf][2] = __expf(sacc[nf][2] - mx_b);
            sacc[nf][3] = __expf(sacc[nf][3] - mx_b);
            sum_a += sacc[nf][0] + sacc[nf][1];
            sum_b += sacc[nf][2] + sacc[nf][3];
        }
        sum_a += __shfl_xor_sync(0xffffffffu, sum_a, 1);
        sum_a += __shfl_xor_sync(0xffffffffu, sum_a, 2);
        sum_b += __shfl_xor_sync(0xffffffffu, sum_b, 1);
        sum_b += __shfl_xor_sync(0xffffffffu, sum_b, 2);
        const float inv_a = 1.0f / sum_a, inv_b = 1.0f / sum_b;

        // ---- pack P into A-fragments (fp16) ----
        uint32_t pah[8][4];
#pragma unroll
        for (int s = 0; s < 8; s++) {
#pragma unroll
            for (int hf = 0; hf < 2; hf++) {
                int nf = 2 * s + hf;
                __half2 p01 = __floats2half2_rn(sacc[nf][0] * inv_a,
                                                sacc[nf][1] * inv_a);
                __half2 p23 = __floats2half2_rn(sacc[nf][2] * inv_b,
                                                sacc[nf][3] * inv_b);
                pah[s][2 * hf]     = *(uint32_t*)&p01;
                pah[s][2 * hf + 1] = *(uint32_t*)&p23;
            }
        }

        // ---- O += P V : single pass, V via ldmatrix.trans ----
#pragma unroll
        for (int s = 0; s < 8; s++) {
#pragma unroll
            for (int nfp = 0; nfp < 4; nfp++) {
                uint32_t off = (uint32_t)((s * 16 * KVS + nfp * 16) * 2);
                uint32_t bh0, bh1, bh2, bh3;
                ldsm4t(bh0, bh1, bh2, bh3, vhb + off + vmofs);
                mma16816(oacc[2 * nfp],     pah[s], bh0, bh1);
                mma16816(oacc[2 * nfp + 1], pah[s], bh2, bh3);
            }
        }
    }

    // ---- write O ----
#pragma unroll
    for (int nf = 0; nf < 8; nf++) {
        size_t r0 = (size_t)(qrow + w * 16 + g) * HS + nf * 8 + 2 * tg;
        size_t r1 = (size_t)(qrow + w * 16 + g + 8) * HS + nf * 8 + 2 * tg;
        *(float2*)&out[r0] = make_float2(oacc[nf][0], oacc[nf][1]);
        *(float2*)&out[r1] = make_float2(oacc[nf][2], oacc[nf][3]);
    }
}

// ---------------------------------------------------------------------------
extern "C" void kernel_launch(void* const* d_in, const int* in_sizes, int n_in,
                              void* d_out, int out_size)
{
    const float* x  = (const float*)d_in[0];
    const float* Wq = (const float*)d_in[1];
    const float* Wk = (const float*)d_in[2];
    const float* Wv = (const float*)d_in[3];
    float* out = (float*)d_out;

    wsplit_kernel<<<192, 256>>>(Wq, Wk, Wv);

    int qsmemB = (128 * QXS + 2 * 192 * QWS) * (int)sizeof(__half);  // 40960
    cudaFuncSetAttribute(qkv_kernel, cudaFuncAttributeMaxDynamicSharedMemorySize, qsmemB);
    qkv_kernel<<<512, 256, qsmemB>>>(x);

    int asmemB = 2 * 128 * KVS * (int)sizeof(__half);   // 36864
    cudaFuncSetAttribute(attn_kernel, cudaFuncAttributeMaxDynamicSharedMemorySize, asmemB);
    attn_kernel<<<1024, 128, asmemB>>>(out);
}

// round 15
// speedup vs baseline: 1.8337x; 1.0649x over previous
#include <cuda_runtime.h>
#include <cuda_fp16.h>
#include <cstdint>

// Shapes: n=8, b=64, h=128, f=256, hs=64
#define N_SEQ 8
#define B_DIM 64
#define H_DIM 128
#define F_DIM 256
#define HS 64
#define M_TOTAL (N_SEQ * B_DIM * H_DIM)   // 65536 rows

// fp16 Q,K,V (Q pre-scaled by 1/16). Projections computed split-2
// (x_hi * [W_hi + W_lo], fp32 accum) then rounded once to fp16.
__device__ __half g_Qh[M_TOTAL * HS];
__device__ __half g_Kh[M_TOTAL * HS];
__device__ __half g_Vh[M_TOTAL * HS];
// W transposed+split: [192 out-cols][256 k], fp16 hi/lo (L2-resident)
__device__ __half g_Wth[192 * 256], g_Wtl[192 * 256];

__device__ __forceinline__ void split2h(float x, __half& h, __half& l) {
    h = __float2half(x);
    l = __float2half(x - __half2float(h));
}

__device__ __forceinline__ uint32_t smem_u32(const void* p) {
    uint32_t a;
    asm("{ .reg .u64 t; cvta.to.shared.u64 t, %1; cvt.u32.u64 %0, t; }" : "=r"(a) : "l"(p));
    return a;
}

// fp16 mma, f32 accumulate
__device__ __forceinline__ void mma16816(float* c, const uint32_t* a,
                                         uint32_t b0, uint32_t b1) {
    asm volatile(
        "mma.sync.aligned.m16n8k16.row.col.f32.f16.f16.f32 "
        "{%0,%1,%2,%3},{%4,%5,%6,%7},{%8,%9},{%0,%1,%2,%3};"
        : "+f"(c[0]), "+f"(c[1]), "+f"(c[2]), "+f"(c[3])
        : "r"(a[0]), "r"(a[1]), "r"(a[2]), "r"(a[3]), "r"(b0), "r"(b1));
}
__device__ __forceinline__ void ldsm4(uint32_t& r0, uint32_t& r1, uint32_t& r2,
                                      uint32_t& r3, uint32_t addr) {
    asm volatile("ldmatrix.sync.aligned.m8n8.x4.shared.b16 {%0,%1,%2,%3}, [%4];"
                 : "=r"(r0), "=r"(r1), "=r"(r2), "=r"(r3) : "r"(addr));
}
__device__ __forceinline__ void ldsm4t(uint32_t& r0, uint32_t& r1, uint32_t& r2,
                                       uint32_t& r3, uint32_t addr) {
    asm volatile("ldmatrix.sync.aligned.m8n8.x4.trans.shared.b16 {%0,%1,%2,%3}, [%4];"
                 : "=r"(r0), "=r"(r1), "=r"(r2), "=r"(r3) : "r"(addr));
}

// ---------------------------------------------------------------------------
// Kernel W: one-time W transpose + fp16 hi/lo split. grid 192, block 256.
// ---------------------------------------------------------------------------
__global__ __launch_bounds__(256) void wsplit_kernel(
    const float* __restrict__ Wq,
    const float* __restrict__ Wk,
    const float* __restrict__ Wv)
{
    int idx = blockIdx.x * 256 + threadIdx.x;   // 0..49151
    int ng = idx >> 8;                          // 0..191
    int k  = idx & 255;
    const float* W = (ng < 64) ? Wq : (ng < 128) ? Wk : Wv;
    float v = W[(size_t)k * HS + (ng & 63)];
    __half h, l;
    split2h(v, h, l);
    g_Wth[ng * 256 + k] = h;
    g_Wtl[ng * 256 + k] = l;
}

// ---------------------------------------------------------------------------
// Kernel A: merged QKV GEMM, split-2 (x hi-only; W hi/lo).
// RESHAPED: grid 1024, block 128 (4 warps), 3 CTAs/SM.
// CTA: 64 rows x 192 cols; warp: 16 rows x 192 cols (24 acc frags).
// K chunks of 32 (2 k-steps). Waves 3.46 -> 2.3, warps/SM 8 -> 12.
// ---------------------------------------------------------------------------
#define QXS 40
#define QWS 40

__global__ __launch_bounds__(128, 3) void qkv_kernel(const float* __restrict__ x)
{
    extern __shared__ __half qsm[];
    __half* xs_hi = qsm;                        // [64][40]
    __half* wt_hi = xs_hi + 64 * QXS;           // [192][40]
    __half* wt_lo = wt_hi + 192 * QWS;

    const int t    = threadIdx.x;
    const int w    = t >> 5;                    // 0..3
    const int lane = t & 31;
    const int g    = lane >> 2;
    const int tg   = lane & 3;
    const int rowBase = blockIdx.x * 64;

    const uint32_t xhb = smem_u32(xs_hi);
    const uint32_t whb = smem_u32(wt_hi), wlb = smem_u32(wt_lo);

    const uint32_t aofs  = (uint32_t)(((lane & 15) * QXS + ((lane >> 4) << 3)) * 2);
    const uint32_t bofs  = (uint32_t)((((lane & 7) + ((lane >> 4) << 3)) * QWS
                                      + (((lane >> 3) & 1) << 3)) * 2);

    float acc[24][4];
#pragma unroll
    for (int nf = 0; nf < 24; nf++)
#pragma unroll
        for (int c = 0; c < 4; c++) acc[nf][c] = 0.f;

    for (int k0 = 0; k0 < F_DIM; k0 += 32) {
#pragma unroll
        for (int p = 0; p < 4; p++) {   // x tile 64x32 -> fp16 hi (512 tasks)
            int e = t + p * 128;
            int row = e >> 3;
            int lc  = (e & 7) * 4;
            float4 v = *(const float4*)&x[(size_t)(rowBase + row) * F_DIM + k0 + lc];
            *(__half2*)&xs_hi[row * QXS + lc]     = __floats2half2_rn(v.x, v.y);
            *(__half2*)&xs_hi[row * QXS + lc + 2] = __floats2half2_rn(v.z, v.w);
        }
#pragma unroll
        for (int p = 0; p < 12; p++) {  // Wt tiles 192x32 hi+lo (1536 tasks)
            int e = t + p * 128;
            int arr = (e >= 768) ? 1 : 0;
            int idx = e - arr * 768;
            int row = idx >> 2;
            int ch  = idx & 3;
            const __half* src = arr ? g_Wtl : g_Wth;
            __half* dst = arr ? wt_lo : wt_hi;
            *(uint4*)&dst[row * QWS + ch * 8] =
                *(const uint4*)&src[row * 256 + k0 + ch * 8];
        }
        __syncthreads();

#pragma unroll
        for (int ks = 0; ks < 2; ks++) {
            uint32_t ah[4];
            uint32_t off = (uint32_t)((w * 16 * QXS + ks * 16) * 2);
            ldsm4(ah[0], ah[1], ah[2], ah[3], xhb + off + aofs);
#pragma unroll
            for (int nf2 = 0; nf2 < 12; nf2++) {
                uint32_t boff = (uint32_t)((nf2 * 16 * QWS + ks * 16) * 2);
                uint32_t bh0, bh1, bh2, bh3, bl0, bl1, bl2, bl3;
                ldsm4(bh0, bh1, bh2, bh3, whb + boff + bofs);
                ldsm4(bl0, bl1, bl2, bl3, wlb + boff + bofs);
                mma16816(acc[2 * nf2],     ah, bh0, bh1);
                mma16816(acc[2 * nf2],     ah, bl0, bl1);
                mma16816(acc[2 * nf2 + 1], ah, bh2, bh3);
                mma16816(acc[2 * nf2 + 1], ah, bl2, bl3);
            }
        }
        __syncthreads();
    }

    // epilogue: round to fp16 once; route to Q/K/V (Q scaled by 1/16)
#pragma unroll
    for (int nf = 0; nf < 24; nf++) {
        int ncol = nf * 8;
        int m    = ncol >> 6;           // 0:Q 1:K 2:V
        int col  = (ncol & 63) + 2 * tg;
        float sc = (m == 0) ? 0.0625f : 1.0f;
        __half* __restrict__ outH = (m == 0) ? g_Qh : (m == 1) ? g_Kh : g_Vh;
        size_t r0 = (size_t)(rowBase + w * 16 + g) * HS + col;
        size_t r1 = (size_t)(rowBase + w * 16 + g + 8) * HS + col;
        *(__half2*)&outH[r0] = __floats2half2_rn(acc[nf][0] * sc, acc[nf][1] * sc);
        *(__half2*)&outH[r1] = __floats2half2_rn(acc[nf][2] * sc, acc[nf][3] * sc);
    }
}

// ---------------------------------------------------------------------------
// Kernel B: FA-style attention, fp16 mma f32-accum, single-pass S and PV.
// grid 1024 = (j,b,half), block 128 (4 warps), pinned 3 CTAs/SM.
// K + V tiles in smem stride 72. (structure unchanged from R14)
// ---------------------------------------------------------------------------
#define KVS 72

__global__ __launch_bounds__(128, 3) void attn_kernel(float* __restrict__ out)
{
    extern __shared__ __half sm[];
    __half* kh = sm;
    __half* vh = kh + 128 * KVS;

    const int t    = threadIdx.x;
    const int w    = t >> 5;
    const int lane = t & 31;
    const int g    = lane >> 2;
    const int tg   = lane & 3;
    const int j    = blockIdx.x & 7;
    const int b    = (blockIdx.x >> 3) & 63;
    const int half_ = blockIdx.x >> 9;
    const int qrow = (j * B_DIM + b) * H_DIM + half_ * 64;

    const uint32_t khb = smem_u32(kh);
    const uint32_t vhb = smem_u32(vh);

    const uint32_t aofs  = (uint32_t)(((lane & 15) * KVS + ((lane >> 4) << 3)) * 2);
    const uint32_t kmofs = (uint32_t)((((lane & 7) + ((lane >> 4) << 3)) * KVS
                                       + (((lane >> 3) & 1) << 3)) * 2);
    const uint32_t vmofs = (uint32_t)((((lane & 7) + (((lane >> 3) & 1) << 3)) * KVS
                                       + ((lane >> 4) << 3)) * 2);

    // ---- stage Q (64 rows) into kh, hoist A-frags ----
#pragma unroll
    for (int p = 0; p < 4; p++) {
        int e = t + p * 128;            // 512 uint4 tasks
        int row = e >> 3;
        int ch  = e & 7;
        *(uint4*)&kh[row * KVS + ch * 8] =
            *(const uint4*)&g_Qh[(size_t)(qrow + row) * HS + ch * 8];
    }
    __syncthreads();

    uint32_t qhf[4][4];
#pragma unroll
    for (int ks = 0; ks < 4; ks++) {
        uint32_t off = (uint32_t)((w * 16 * KVS + ks * 16) * 2);
        ldsm4(qhf[ks][0], qhf[ks][1], qhf[ks][2], qhf[ks][3], khb + off + aofs);
    }

    float oacc[8][4];
#pragma unroll
    for (int nf = 0; nf < 8; nf++)
#pragma unroll
        for (int c = 0; c < 4; c++) oacc[nf][c] = 0.f;

    for (int i = 0; i < N_SEQ; i++) {
        __syncthreads();   // prev PV reads done (and Q-frag loads at i==0)
        const int kb0 = (i * B_DIM + b) * H_DIM;
        // copy K + V: 2048 uint4 tasks, 16/thread
#pragma unroll 8
        for (int p = 0; p < 16; p++) {
            int e = t + p * 128;
            int arr = e >> 10;          // 0: K, 1: V
            int idx = e & 1023;
            int row = idx >> 3;
            int ch  = idx & 7;
            const __half* src = arr ? g_Vh : g_Kh;
            __half* dst = arr ? vh : kh;
            *(uint4*)&dst[row * KVS + ch * 8] =
                *(const uint4*)&src[(size_t)(kb0 + row) * HS + ch * 8];
        }
        __syncthreads();

        // ---- S = Q K^T : single pass, 16 rows x 128 keys in registers ----
        float sacc[16][4];
#pragma unroll
        for (int nf = 0; nf < 16; nf++)
#pragma unroll
            for (int c = 0; c < 4; c++) sacc[nf][c] = 0.f;

#pragma unroll
        for (int ks = 0; ks < 4; ks++) {
#pragma unroll
            for (int nfp = 0; nfp < 8; nfp++) {
                uint32_t off = (uint32_t)((nfp * 16 * KVS + ks * 16) * 2);
                uint32_t bh0, bh1, bh2, bh3;
                ldsm4(bh0, bh1, bh2, bh3, khb + off + kmofs);
                mma16816(sacc[2 * nfp],     qhf[ks], bh0, bh1);
                mma16816(sacc[2 * nfp + 1], qhf[ks], bh2, bh3);
            }
        }

        // ---- softmax in registers (rows g and g+8 of this warp's 16) ----
        float mx_a = sacc[0][0], mx_b = sacc[0][2];
#pragma unroll
        for (int nf = 0; nf < 16; nf++) {
            mx_a = fmaxf(mx_a, fmaxf(sacc[nf][0], sacc[nf][1]));
            mx_b = fmaxf(mx_b, fmaxf(sacc[nf][2], sacc[nf][3]));
        }
        mx_a = fmaxf(mx_a, __shfl_xor_sync(0xffffffffu, mx_a, 1));
        mx_a = fmaxf(mx_a, __shfl_xor_sync(0xffffffffu, mx_a, 2));
        mx_b = fmaxf(mx_b, __shfl_xor_sync(0xffffffffu, mx_b, 1));
        mx_b = fmaxf(mx_b, __shfl_xor_sync(0xffffffffu, mx_b, 2));
        float sum_a = 0.f, sum_b = 0.f;
#pragma unroll
        for (int nf = 0; nf < 16; nf++) {
            sacc[nf][0] = __expf(sacc[nf][0] - mx_a);
            sacc[nf][1] = __expf(sacc[nf][1] - mx_a);
            sacc[nf][2] = __expf(sacc[nf][2] - mx_b);
            sacc[nf][3] = __expf(sacc[nf][3] - mx_b);
            sum_a += sacc[nf][0] + sacc[nf][1];
            sum_b += sacc[nf][2] + sacc[nf][3];
        }
        sum_a += __shfl_xor_sync(0xffffffffu, sum_a, 1);
        sum_a += __shfl_xor_sync(0xffffffffu, sum_a, 2);
        sum_b += __shfl_xor_sync(0xffffffffu, sum_b, 1);
        sum_b += __shfl_xor_sync(0xffffffffu, sum_b, 2);
        const float inv_a = 1.0f / sum_a, inv_b = 1.0f / sum_b;

        // ---- pack P into A-fragments (fp16) ----
        uint32_t pah[8][4];
#pragma unroll
        for (int s = 0; s < 8; s++) {
#pragma unroll
            for (int hf = 0; hf < 2; hf++) {
                int nf = 2 * s + hf;
                __half2 p01 = __floats2half2_rn(sacc[nf][0] * inv_a,
                                                sacc[nf][1] * inv_a);
                __half2 p23 = __floats2half2_rn(sacc[nf][2] * inv_b,
                                                sacc[nf][3] * inv_b);
                pah[s][2 * hf]     = *(uint32_t*)&p01;
                pah[s][2 * hf + 1] = *(uint32_t*)&p23;
            }
        }

        // ---- O += P V : single pass, V via ldmatrix.trans ----
#pragma unroll
        for (int s = 0; s < 8; s++) {
#pragma unroll
            for (int nfp = 0; nfp < 4; nfp++) {
                uint32_t off = (uint32_t)((s * 16 * KVS + nfp * 16) * 2);
                uint32_t bh0, bh1, bh2, bh3;
                ldsm4t(bh0, bh1, bh2, bh3, vhb + off + vmofs);
                mma16816(oacc[2 * nfp],     pah[s], bh0, bh1);
                mma16816(oacc[2 * nfp + 1], pah[s], bh2, bh3);
            }
        }
    }

    // ---- write O ----
#pragma unroll
    for (int nf = 0; nf < 8; nf++) {
        size_t r0 = (size_t)(qrow + w * 16 + g) * HS + nf * 8 + 2 * tg;
        size_t r1 = (size_t)(qrow + w * 16 + g + 8) * HS + nf * 8 + 2 * tg;
        *(float2*)&out[r0] = make_float2(oacc[nf][0], oacc[nf][1]);
        *(float2*)&out[r1] = make_float2(oacc[nf][2], oacc[nf][3]);
    }
}

// ---------------------------------------------------------------------------
extern "C" void kernel_launch(void* const* d_in, const int* in_sizes, int n_in,
                              void* d_out, int out_size)
{
    const float* x  = (const float*)d_in[0];
    const float* Wq = (const float*)d_in[1];
    const float* Wk = (const float*)d_in[2];
    const float* Wv = (const float*)d_in[3];
    float* out = (float*)d_out;

    wsplit_kernel<<<192, 256>>>(Wq, Wk, Wv);

    int qsmemB = (64 * QXS + 2 * 192 * QWS) * (int)sizeof(__half);  // 35840
    cudaFuncSetAttribute(qkv_kernel, cudaFuncAttributeMaxDynamicSharedMemorySize, qsmemB);
    qkv_kernel<<<1024, 128, qsmemB>>>(x);

    int asmemB = 2 * 128 * KVS * (int)sizeof(__half);   // 36864
    cudaFuncSetAttribute(attn_kernel, cudaFuncAttributeMaxDynamicSharedMemorySize, asmemB);
    attn_kernel<<<1024, 128, asmemB>>>(out);
}

// round 16
// speedup vs baseline: 1.8340x; 1.0002x over previous
#include <cuda_runtime.h>
#include <cuda_fp16.h>
#include <cstdint>

// Shapes: n=8, b=64, h=128, f=256, hs=64
#define N_SEQ 8
#define B_DIM 64
#define H_DIM 128
#define F_DIM 256
#define HS 64
#define M_TOTAL (N_SEQ * B_DIM * H_DIM)   // 65536 rows

// fp16 Q,K,V (Q pre-scaled by 1/16). Projections computed split-2
// (x_hi * [W_hi + W_lo], fp32 accum) then rounded once to fp16.
__device__ __half g_Qh[M_TOTAL * HS];
__device__ __half g_Kh[M_TOTAL * HS];
__device__ __half g_Vh[M_TOTAL * HS];
// W transposed+split: [192 out-cols][256 k], fp16 hi/lo (L2-resident)
__device__ __half g_Wth[192 * 256], g_Wtl[192 * 256];

__device__ __forceinline__ void split2h(float x, __half& h, __half& l) {
    h = __float2half(x);
    l = __float2half(x - __half2float(h));
}

__device__ __forceinline__ uint32_t smem_u32(const void* p) {
    uint32_t a;
    asm("{ .reg .u64 t; cvta.to.shared.u64 t, %1; cvt.u32.u64 %0, t; }" : "=r"(a) : "l"(p));
    return a;
}

// fp16 mma, f32 accumulate
__device__ __forceinline__ void mma16816(float* c, const uint32_t* a,
                                         uint32_t b0, uint32_t b1) {
    asm volatile(
        "mma.sync.aligned.m16n8k16.row.col.f32.f16.f16.f32 "
        "{%0,%1,%2,%3},{%4,%5,%6,%7},{%8,%9},{%0,%1,%2,%3};"
        : "+f"(c[0]), "+f"(c[1]), "+f"(c[2]), "+f"(c[3])
        : "r"(a[0]), "r"(a[1]), "r"(a[2]), "r"(a[3]), "r"(b0), "r"(b1));
}
__device__ __forceinline__ void ldsm4(uint32_t& r0, uint32_t& r1, uint32_t& r2,
                                      uint32_t& r3, uint32_t addr) {
    asm volatile("ldmatrix.sync.aligned.m8n8.x4.shared.b16 {%0,%1,%2,%3}, [%4];"
                 : "=r"(r0), "=r"(r1), "=r"(r2), "=r"(r3) : "r"(addr));
}
__device__ __forceinline__ void ldsm4t(uint32_t& r0, uint32_t& r1, uint32_t& r2,
                                       uint32_t& r3, uint32_t addr) {
    asm volatile("ldmatrix.sync.aligned.m8n8.x4.trans.shared.b16 {%0,%1,%2,%3}, [%4];"
                 : "=r"(r0), "=r"(r1), "=r"(r2), "=r"(r3) : "r"(addr));
}

// ---------------------------------------------------------------------------
// Kernel W: one-time W transpose + fp16 hi/lo split. grid 192, block 256.
// ---------------------------------------------------------------------------
__global__ __launch_bounds__(256) void wsplit_kernel(
    const float* __restrict__ Wq,
    const float* __restrict__ Wk,
    const float* __restrict__ Wv)
{
    int idx = blockIdx.x * 256 + threadIdx.x;   // 0..49151
    int ng = idx >> 8;                          // 0..191
    int k  = idx & 255;
    const float* W = (ng < 64) ? Wq : (ng < 128) ? Wk : Wv;
    float v = W[(size_t)k * HS + (ng & 63)];
    __half h, l;
    split2h(v, h, l);
    g_Wth[ng * 256 + k] = h;
    g_Wtl[ng * 256 + k] = l;
}

// ---------------------------------------------------------------------------
// Kernel A: merged QKV GEMM, split-2 (x hi-only; W hi/lo).
// RESHAPED: grid 1024, block 128 (4 warps), 3 CTAs/SM.
// CTA: 64 rows x 192 cols; warp: 16 rows x 192 cols (24 acc frags).
// K chunks of 32 (2 k-steps). Waves 3.46 -> 2.3, warps/SM 8 -> 12.
// ---------------------------------------------------------------------------
#define QXS 40
#define QWS 40

__global__ __launch_bounds__(128, 3) void qkv_kernel(const float* __restrict__ x)
{
    extern __shared__ __half qsm[];
    __half* xs_hi = qsm;                        // [64][40]
    __half* wt_hi = xs_hi + 64 * QXS;           // [192][40]
    __half* wt_lo = wt_hi + 192 * QWS;

    const int t    = threadIdx.x;
    const int w    = t >> 5;                    // 0..3
    const int lane = t & 31;
    const int g    = lane >> 2;
    const int tg   = lane & 3;
    const int rowBase = blockIdx.x * 64;

    const uint32_t xhb = smem_u32(xs_hi);
    const uint32_t whb = smem_u32(wt_hi), wlb = smem_u32(wt_lo);

    const uint32_t aofs  = (uint32_t)(((lane & 15) * QXS + ((lane >> 4) << 3)) * 2);
    const uint32_t bofs  = (uint32_t)((((lane & 7) + ((lane >> 4) << 3)) * QWS
                                      + (((lane >> 3) & 1) << 3)) * 2);

    float acc[24][4];
#pragma unroll
    for (int nf = 0; nf < 24; nf++)
#pragma unroll
        for (int c = 0; c < 4; c++) acc[nf][c] = 0.f;

    for (int k0 = 0; k0 < F_DIM; k0 += 32) {
#pragma unroll
        for (int p = 0; p < 4; p++) {   // x tile 64x32 -> fp16 hi (512 tasks)
            int e = t + p * 128;
            int row = e >> 3;
            int lc  = (e & 7) * 4;
            float4 v = *(const float4*)&x[(size_t)(rowBase + row) * F_DIM + k0 + lc];
            *(__half2*)&xs_hi[row * QXS + lc]     = __floats2half2_rn(v.x, v.y);
            *(__half2*)&xs_hi[row * QXS + lc + 2] = __floats2half2_rn(v.z, v.w);
        }
#pragma unroll
        for (int p = 0; p < 12; p++) {  // Wt tiles 192x32 hi+lo (1536 tasks)
            int e = t + p * 128;
            int arr = (e >= 768) ? 1 : 0;
            int idx = e - arr * 768;
            int row = idx >> 2;
            int ch  = idx & 3;
            const __half* src = arr ? g_Wtl : g_Wth;
            __half* dst = arr ? wt_lo : wt_hi;
            *(uint4*)&dst[row * QWS + ch * 8] =
                *(const uint4*)&src[row * 256 + k0 + ch * 8];
        }
        __syncthreads();

#pragma unroll
        for (int ks = 0; ks < 2; ks++) {
            uint32_t ah[4];
            uint32_t off = (uint32_t)((w * 16 * QXS + ks * 16) * 2);
            ldsm4(ah[0], ah[1], ah[2], ah[3], xhb + off + aofs);
#pragma unroll
            for (int nf2 = 0; nf2 < 12; nf2++) {
                uint32_t boff = (uint32_t)((nf2 * 16 * QWS + ks * 16) * 2);
                uint32_t bh0, bh1, bh2, bh3, bl0, bl1, bl2, bl3;
                ldsm4(bh0, bh1, bh2, bh3, whb + boff + bofs);
                ldsm4(bl0, bl1, bl2, bl3, wlb + boff + bofs);
                mma16816(acc[2 * nf2],     ah, bh0, bh1);
                mma16816(acc[2 * nf2],     ah, bl0, bl1);
                mma16816(acc[2 * nf2 + 1], ah, bh2, bh3);
                mma16816(acc[2 * nf2 + 1], ah, bl2, bl3);
            }
        }
        __syncthreads();
    }

    // epilogue: round to fp16 once; route to Q/K/V (Q scaled by 1/16)
#pragma unroll
    for (int nf = 0; nf < 24; nf++) {
        int ncol = nf * 8;
        int m    = ncol >> 6;           // 0:Q 1:K 2:V
        int col  = (ncol & 63) + 2 * tg;
        float sc = (m == 0) ? 0.0625f : 1.0f;
        __half* __restrict__ outH = (m == 0) ? g_Qh : (m == 1) ? g_Kh : g_Vh;
        size_t r0 = (size_t)(rowBase + w * 16 + g) * HS + col;
        size_t r1 = (size_t)(rowBase + w * 16 + g + 8) * HS + col;
        *(__half2*)&outH[r0] = __floats2half2_rn(acc[nf][0] * sc, acc[nf][1] * sc);
        *(__half2*)&outH[r1] = __floats2half2_rn(acc[nf][2] * sc, acc[nf][3] * sc);
    }
}

// ---------------------------------------------------------------------------
// Kernel B: FA-style attention, fp16 mma f32-accum, single-pass S and PV.
// grid 1024 = (j,b,half), block 128 (4 warps), pinned 3 CTAs/SM.
// K + V tiles in smem stride 72. (structure unchanged from R14)
// ---------------------------------------------------------------------------
#define KVS 72

__global__ __launch_bounds__(128, 3) void attn_kernel(float* __restrict__ out)
{
    extern __shared__ __half sm[];
    __half* kh = sm;
    __half* vh = kh + 128 * KVS;

    const int t    = threadIdx.x;
    const int w    = t >> 5;
    const int lane = t & 31;
    const int g    = lane >> 2;
    const int tg   = lane & 3;
    const int j    = blockIdx.x & 7;
    const int b    = (blockIdx.x >> 3) & 63;
    const int half_ = blockIdx.x >> 9;
    const int qrow = (j * B_DIM + b) * H_DIM + half_ * 64;

    const uint32_t khb = smem_u32(kh);
    const uint32_t vhb = smem_u32(vh);

    const uint32_t aofs  = (uint32_t)(((lane & 15) * KVS + ((lane >> 4) << 3)) * 2);
    const uint32_t kmofs = (uint32_t)((((lane & 7) + ((lane >> 4) << 3)) * KVS
                                       + (((lane >> 3) & 1) << 3)) * 2);
    const uint32_t vmofs = (uint32_t)((((lane & 7) + (((lane >> 3) & 1) << 3)) * KVS
                                       + ((lane >> 4) << 3)) * 2);

    // ---- stage Q (64 rows) into kh, hoist A-frags ----
#pragma unroll
    for (int p = 0; p < 4; p++) {
        int e = t + p * 128;            // 512 uint4 tasks
        int row = e >> 3;
        int ch  = e & 7;
        *(uint4*)&kh[row * KVS + ch * 8] =
            *(const uint4*)&g_Qh[(size_t)(qrow + row) * HS + ch * 8];
    }
    __syncthreads();

    uint32_t qhf[4][4];
#pragma unroll
    for (int ks = 0; ks < 4; ks++) {
        uint32_t off = (uint32_t)((w * 16 * KVS + ks * 16) * 2);
        ldsm4(qhf[ks][0], qhf[ks][1], qhf[ks][2], qhf[ks][3], khb + off + aofs);
    }

    float oacc[8][4];
#pragma unroll
    for (int nf = 0; nf < 8; nf++)
#pragma unroll
        for (int c = 0; c < 4; c++) oacc[nf][c] = 0.f;

    for (int i = 0; i < N_SEQ; i++) {
        __syncthreads();   // prev PV reads done (and Q-frag loads at i==0)
        const int kb0 = (i * B_DIM + b) * H_DIM;
        // copy K + V: 2048 uint4 tasks, 16/thread
#pragma unroll 8
        for (int p = 0; p < 16; p++) {
            int e = t + p * 128;
            int arr = e >> 10;          // 0: K, 1: V
            int idx = e & 1023;
            int row = idx >> 3;
            int ch  = idx & 7;
            const __half* src = arr ? g_Vh : g_Kh;
            __half* dst = arr ? vh : kh;
            *(uint4*)&dst[row * KVS + ch * 8] =
                *(const uint4*)&src[(size_t)(kb0 + row) * HS + ch * 8];
        }
        __syncthreads();

        // ---- S = Q K^T : single pass, 16 rows x 128 keys in registers ----
        float sacc[16][4];
#pragma unroll
        for (int nf = 0; nf < 16; nf++)
#pragma unroll
            for (int c = 0; c < 4; c++) sacc[nf][c] = 0.f;

#pragma unroll
        for (int ks = 0; ks < 4; ks++) {
#pragma unroll
            for (int nfp = 0; nfp < 8; nfp++) {
                uint32_t off = (uint32_t)((nfp * 16 * KVS + ks * 16) * 2);
                uint32_t bh0, bh1, bh2, bh3;
                ldsm4(bh0, bh1, bh2, bh3, khb + off + kmofs);
                mma16816(sacc[2 * nfp],     qhf[ks], bh0, bh1);
                mma16816(sacc[2 * nfp + 1], qhf[ks], bh2, bh3);
            }
        }

        // ---- softmax in registers (rows g and g+8 of this warp's 16) ----
        float mx_a = sacc[0][0], mx_b = sacc[0][2];
#pragma unroll
        for (int nf = 0; nf < 16; nf++) {
            mx_a = fmaxf(mx_a, fmaxf(sacc[nf][0], sacc[nf][1]));
            mx_b = fmaxf(mx_b, fmaxf(sacc[nf][2], sacc[nf][3]));
        }
        mx_a = fmaxf(mx_a, __shfl_xor_sync(0xffffffffu, mx_a, 1));
        mx_a = fmaxf(mx_a, __shfl_xor_sync(0xffffffffu, mx_a, 2));
        mx_b = fmaxf(mx_b, __shfl_xor_sync(0xffffffffu, mx_b, 1));
        mx_b = fmaxf(mx_b, __shfl_xor_sync(0xffffffffu, mx_b, 2));
        float sum_a = 0.f, sum_b = 0.f;
#pragma unroll
        for (int nf = 0; nf < 16; nf++) {
            sacc[nf][0] = __expf(sacc[nf][0] - mx_a);
            sacc[nf][1] = __expf(sacc[nf][1] - mx_a);
            sacc[nf][2] = __expf(sacc[nf][2] - mx_b);
            sacc[nf][3] = __expf(sacc[nf][3] - mx_b);
            sum_a += sacc[nf][0] + sacc[nf][1];
            sum_b += sacc[nf][2] + sacc[nf][3];
        }
        sum_a += __shfl_xor_sync(0xffffffffu, sum_a, 1);
        sum_a += __shfl_xor_sync(0xffffffffu, sum_a, 2);
        sum_b += __shfl_xor_sync(0xffffffffu, sum_b, 1);
        sum_b += __shfl_xor_sync(0xffffffffu, sum_b, 2);
        const float inv_a = 1.0f / sum_a, inv_b = 1.0f / sum_b;

        // ---- pack P into A-fragments (fp16) ----
        uint32_t pah[8][4];
#pragma unroll
        for (int s = 0; s < 8; s++) {
#pragma unroll
            for (int hf = 0; hf < 2; hf++) {
                int nf = 2 * s + hf;
                __half2 p01 = __floats2half2_rn(sacc[nf][0] * inv_a,
                                                sacc[nf][1] * inv_a);
                __half2 p23 = __floats2half2_rn(sacc[nf][2] * inv_b,
                                                sacc[nf][3] * inv_b);
                pah[s][2 * hf]     = *(uint32_t*)&p01;
                pah[s][2 * hf + 1] = *(uint32_t*)&p23;
            }
        }

        // ---- O += P V : single pass, V via ldmatrix.trans ----
#pragma unroll
        for (int s = 0; s < 8; s++) {
#pragma unroll
            for (int nfp = 0; nfp < 4; nfp++) {
                uint32_t off = (uint32_t)((s * 16 * KVS + nfp * 16) * 2);
                uint32_t bh0, bh1, bh2, bh3;
                ldsm4t(bh0, bh1, bh2, bh3, vhb + off + vmofs);
                mma16816(oacc[2 * nfp],     pah[s], bh0, bh1);
                mma16816(oacc[2 * nfp + 1], pah[s], bh2, bh3);
            }
        }
    }

    // ---- write O ----
#pragma unroll
    for (int nf = 0; nf < 8; nf++) {
        size_t r0 = (size_t)(qrow + w * 16 + g) * HS + nf * 8 + 2 * tg;
        size_t r1 = (size_t)(qrow + w * 16 + g + 8) * HS + nf * 8 + 2 * tg;
        *(float2*)&out[r0] = make_float2(oacc[nf][0], oacc[nf][1]);
        *(float2*)&out[r1] = make_float2(oacc[nf][2], oacc[nf][3]);
    }
}

// ---------------------------------------------------------------------------
extern "C" void kernel_launch(void* const* d_in, const int* in_sizes, int n_in,
                              void* d_out, int out_size)
{
    const float* x  = (const float*)d_in[0];
    const float* Wq = (const float*)d_in[1];
    const float* Wk = (const float*)d_in[2];
    const float* Wv = (const float*)d_in[3];
    float* out = (float*)d_out;

    wsplit_kernel<<<192, 256>>>(Wq, Wk, Wv);

    int qsmemB = (64 * QXS + 2 * 192 * QWS) * (int)sizeof(__half);  // 35840
    cudaFuncSetAttribute(qkv_kernel, cudaFuncAttributeMaxDynamicSharedMemorySize, qsmemB);
    qkv_kernel<<<1024, 128, qsmemB>>>(x);

    int asmemB = 2 * 128 * KVS * (int)sizeof(__half);   // 36864
    cudaFuncSetAttribute(attn_kernel, cudaFuncAttributeMaxDynamicSharedMemorySize, asmemB);
    attn_kernel<<<1024, 128, asmemB>>>(out);
}

// round 17
// speedup vs baseline: 1.9250x; 1.0496x over previous
#include <cuda_runtime.h>
#include <cuda_fp16.h>
#include <cstdint>

// Shapes: n=8, b=64, h=128, f=256, hs=64
#define N_SEQ 8
#define B_DIM 64
#define H_DIM 128
#define F_DIM 256
#define HS 64
#define M_TOTAL (N_SEQ * B_DIM * H_DIM)   // 65536 rows

// fp16 Q,K,V (Q pre-scaled by 1/16). Projections computed split-2
// (x_hi * [W_hi + W_lo], fp32 accum) then rounded once to fp16.
__device__ __half g_Qh[M_TOTAL * HS];
__device__ __half g_Kh[M_TOTAL * HS];
__device__ __half g_Vh[M_TOTAL * HS];
// W transposed+split: [192 out-cols][256 k], fp16 hi/lo (L2-resident)
__device__ __half g_Wth[192 * 256], g_Wtl[192 * 256];

__device__ __forceinline__ void split2h(float x, __half& h, __half& l) {
    h = __float2half(x);
    l = __float2half(x - __half2float(h));
}

__device__ __forceinline__ uint32_t smem_u32(const void* p) {
    uint32_t a;
    asm("{ .reg .u64 t; cvta.to.shared.u64 t, %1; cvt.u32.u64 %0, t; }" : "=r"(a) : "l"(p));
    return a;
}

// fp16 mma, f32 accumulate
__device__ __forceinline__ void mma16816(float* c, const uint32_t* a,
                                         uint32_t b0, uint32_t b1) {
    asm volatile(
        "mma.sync.aligned.m16n8k16.row.col.f32.f16.f16.f32 "
        "{%0,%1,%2,%3},{%4,%5,%6,%7},{%8,%9},{%0,%1,%2,%3};"
        : "+f"(c[0]), "+f"(c[1]), "+f"(c[2]), "+f"(c[3])
        : "r"(a[0]), "r"(a[1]), "r"(a[2]), "r"(a[3]), "r"(b0), "r"(b1));
}
__device__ __forceinline__ void ldsm4(uint32_t& r0, uint32_t& r1, uint32_t& r2,
                                      uint32_t& r3, uint32_t addr) {
    asm volatile("ldmatrix.sync.aligned.m8n8.x4.shared.b16 {%0,%1,%2,%3}, [%4];"
                 : "=r"(r0), "=r"(r1), "=r"(r2), "=r"(r3) : "r"(addr));
}
__device__ __forceinline__ void ldsm4t(uint32_t& r0, uint32_t& r1, uint32_t& r2,
                                       uint32_t& r3, uint32_t addr) {
    asm volatile("ldmatrix.sync.aligned.m8n8.x4.trans.shared.b16 {%0,%1,%2,%3}, [%4];"
                 : "=r"(r0), "=r"(r1), "=r"(r2), "=r"(r3) : "r"(addr));
}
__device__ __forceinline__ void cp16(uint32_t dst, const void* src) {
    asm volatile("cp.async.cg.shared.global [%0], [%1], 16;"
                 :: "r"(dst), "l"(src) : "memory");
}
#define CP_COMMIT() asm volatile("cp.async.commit_group;" ::: "memory")
#define CP_WAIT0()  asm volatile("cp.async.wait_group 0;" ::: "memory")

// ---------------------------------------------------------------------------
// Kernel W: one-time W transpose + fp16 hi/lo split. grid 192, block 256.
// ---------------------------------------------------------------------------
__global__ __launch_bounds__(256) void wsplit_kernel(
    const float* __restrict__ Wq,
    const float* __restrict__ Wk,
    const float* __restrict__ Wv)
{
    int idx = blockIdx.x * 256 + threadIdx.x;   // 0..49151
    int ng = idx >> 8;                          // 0..191
    int k  = idx & 255;
    const float* W = (ng < 64) ? Wq : (ng < 128) ? Wk : Wv;
    float v = W[(size_t)k * HS + (ng & 63)];
    __half h, l;
    split2h(v, h, l);
    g_Wth[ng * 256 + k] = h;
    g_Wtl[ng * 256 + k] = l;
}

// ---------------------------------------------------------------------------
// Kernel A: merged QKV GEMM, split-2 (x hi-only; W hi/lo). (unchanged R15)
// grid 1024, block 128 (4 warps), 3 CTAs/SM. CTA 64 rows x 192 cols.
// ---------------------------------------------------------------------------
#define QXS 40
#define QWS 40

__global__ __launch_bounds__(128, 3) void qkv_kernel(const float* __restrict__ x)
{
    extern __shared__ __half qsm[];
    __half* xs_hi = qsm;                        // [64][40]
    __half* wt_hi = xs_hi + 64 * QXS;           // [192][40]
    __half* wt_lo = wt_hi + 192 * QWS;

    const int t    = threadIdx.x;
    const int w    = t >> 5;
    const int lane = t & 31;
    const int g    = lane >> 2;
    const int tg   = lane & 3;
    const int rowBase = blockIdx.x * 64;

    const uint32_t xhb = smem_u32(xs_hi);
    const uint32_t whb = smem_u32(wt_hi), wlb = smem_u32(wt_lo);

    const uint32_t aofs  = (uint32_t)(((lane & 15) * QXS + ((lane >> 4) << 3)) * 2);
    const uint32_t bofs  = (uint32_t)((((lane & 7) + ((lane >> 4) << 3)) * QWS
                                      + (((lane >> 3) & 1) << 3)) * 2);

    float acc[24][4];
#pragma unroll
    for (int nf = 0; nf < 24; nf++)
#pragma unroll
        for (int c = 0; c < 4; c++) acc[nf][c] = 0.f;

    for (int k0 = 0; k0 < F_DIM; k0 += 32) {
#pragma unroll
        for (int p = 0; p < 4; p++) {   // x tile 64x32 -> fp16 hi (512 tasks)
            int e = t + p * 128;
            int row = e >> 3;
            int lc  = (e & 7) * 4;
            float4 v = *(const float4*)&x[(size_t)(rowBase + row) * F_DIM + k0 + lc];
            *(__half2*)&xs_hi[row * QXS + lc]     = __floats2half2_rn(v.x, v.y);
            *(__half2*)&xs_hi[row * QXS + lc + 2] = __floats2half2_rn(v.z, v.w);
        }
#pragma unroll
        for (int p = 0; p < 12; p++) {  // Wt tiles 192x32 hi+lo (1536 tasks)
            int e = t + p * 128;
            int arr = (e >= 768) ? 1 : 0;
            int idx = e - arr * 768;
            int row = idx >> 2;
            int ch  = idx & 3;
            const __half* src = arr ? g_Wtl : g_Wth;
            __half* dst = arr ? wt_lo : wt_hi;
            *(uint4*)&dst[row * QWS + ch * 8] =
                *(const uint4*)&src[row * 256 + k0 + ch * 8];
        }
        __syncthreads();

#pragma unroll
        for (int ks = 0; ks < 2; ks++) {
            uint32_t ah[4];
            uint32_t off = (uint32_t)((w * 16 * QXS + ks * 16) * 2);
            ldsm4(ah[0], ah[1], ah[2], ah[3], xhb + off + aofs);
#pragma unroll
            for (int nf2 = 0; nf2 < 12; nf2++) {
                uint32_t boff = (uint32_t)((nf2 * 16 * QWS + ks * 16) * 2);
                uint32_t bh0, bh1, bh2, bh3, bl0, bl1, bl2, bl3;
                ldsm4(bh0, bh1, bh2, bh3, whb + boff + bofs);
                ldsm4(bl0, bl1, bl2, bl3, wlb + boff + bofs);
                mma16816(acc[2 * nf2],     ah, bh0, bh1);
                mma16816(acc[2 * nf2],     ah, bl0, bl1);
                mma16816(acc[2 * nf2 + 1], ah, bh2, bh3);
                mma16816(acc[2 * nf2 + 1], ah, bl2, bl3);
            }
        }
        __syncthreads();
    }

#pragma unroll
    for (int nf = 0; nf < 24; nf++) {
        int ncol = nf * 8;
        int m    = ncol >> 6;           // 0:Q 1:K 2:V
        int col  = (ncol & 63) + 2 * tg;
        float sc = (m == 0) ? 0.0625f : 1.0f;
        __half* __restrict__ outH = (m == 0) ? g_Qh : (m == 1) ? g_Kh : g_Vh;
        size_t r0 = (size_t)(rowBase + w * 16 + g) * HS + col;
        size_t r1 = (size_t)(rowBase + w * 16 + g + 8) * HS + col;
        *(__half2*)&outH[r0] = __floats2half2_rn(acc[nf][0] * sc, acc[nf][1] * sc);
        *(__half2*)&outH[r1] = __floats2half2_rn(acc[nf][2] * sc, acc[nf][3] * sc);
    }
}

// ---------------------------------------------------------------------------
// Kernel B: FA-style attention with cp.async DOUBLE-BUFFERED K/V tiles.
// grid 1024 = (j,b,half), block 128 (4 warps), 3 CTAs/SM.
// smem: 2 buffers x (K 128x72 + V 128x72) fp16 = 73.7 KB.
// ---------------------------------------------------------------------------
#define KVS 72
#define MATH (128 * KVS)                 // halves per matrix
#define BUFH (2 * MATH)                  // halves per buffer (K+V)

__global__ __launch_bounds__(128, 3) void attn_kernel(float* __restrict__ out)
{
    extern __shared__ __half sm[];
    // layout: buf0: [K][V], buf1: [K][V]

    const int t    = threadIdx.x;
    const int w    = t >> 5;
    const int lane = t & 31;
    const int g    = lane >> 2;
    const int tg   = lane & 3;
    const int j    = blockIdx.x & 7;
    const int b    = (blockIdx.x >> 3) & 63;
    const int half_ = blockIdx.x >> 9;
    const int qrow = (j * B_DIM + b) * H_DIM + half_ * 64;

    const uint32_t smb = smem_u32(sm);

    const uint32_t aofs  = (uint32_t)(((lane & 15) * KVS + ((lane >> 4) << 3)) * 2);
    const uint32_t kmofs = (uint32_t)((((lane & 7) + ((lane >> 4) << 3)) * KVS
                                       + (((lane >> 3) & 1) << 3)) * 2);
    const uint32_t vmofs = (uint32_t)((((lane & 7) + (((lane >> 3) & 1) << 3)) * KVS
                                       + ((lane >> 4) << 3)) * 2);

    // per-thread copy-task coords (16 tasks: 8 per matrix)
    const int c_arr = t >> 6;            // unused; tasks derived per p below

    // ---- stage Q (64 rows) into buf0 K region, hoist A-frags ----
#pragma unroll
    for (int p = 0; p < 4; p++) {
        int e = t + p * 128;            // 512 uint4 tasks
        int row = e >> 3;
        int ch  = e & 7;
        *(uint4*)&sm[row * KVS + ch * 8] =
            *(const uint4*)&g_Qh[(size_t)(qrow + row) * HS + ch * 8];
    }
    __syncthreads();

    uint32_t qhf[4][4];
#pragma unroll
    for (int ks = 0; ks < 4; ks++) {
        uint32_t off = (uint32_t)((w * 16 * KVS + ks * 16) * 2);
        ldsm4(qhf[ks][0], qhf[ks][1], qhf[ks][2], qhf[ks][3], smb + off + aofs);
    }
    __syncthreads();   // all warps done reading Q before prefetch overwrites buf0

    // ---- prologue: prefetch i=0 into buf0 ----
    {
        const int kb0 = (0 * B_DIM + b) * H_DIM;
#pragma unroll
        for (int p = 0; p < 16; p++) {
            int e = t + p * 128;
            int arr = e >> 10;          // 0: K, 1: V
            int idx = e & 1023;
            int row = idx >> 3;
            int ch  = idx & 7;
            const __half* src = arr ? g_Vh : g_Kh;
            uint32_t dst = smb + (uint32_t)((arr * MATH + row * KVS + ch * 8) * 2);
            cp16(dst, &src[(size_t)(kb0 + row) * HS + ch * 8]);
        }
        CP_COMMIT();
    }

    float oacc[8][4];
#pragma unroll
    for (int nf = 0; nf < 8; nf++)
#pragma unroll
        for (int c = 0; c < 4; c++) oacc[nf][c] = 0.f;

    for (int i = 0; i < N_SEQ; i++) {
        const uint32_t cur = smb + (uint32_t)((i & 1) * BUFH * 2);
        CP_WAIT0();
        __syncthreads();   // cur data visible to all; all warps done with nxt buf

        // prefetch i+1 into the other buffer
        if (i + 1 < N_SEQ) {
            const int kb1 = ((i + 1) * B_DIM + b) * H_DIM;
            const uint32_t nxt = smb + (uint32_t)(((i + 1) & 1) * BUFH * 2);
#pragma unroll
            for (int p = 0; p < 16; p++) {
                int e = t + p * 128;
                int arr = e >> 10;
                int idx = e & 1023;
                int row = idx >> 3;
                int ch  = idx & 7;
                const __half* src = arr ? g_Vh : g_Kh;
                uint32_t dst = nxt + (uint32_t)((arr * MATH + row * KVS + ch * 8) * 2);
                cp16(dst, &src[(size_t)(kb1 + row) * HS + ch * 8]);
            }
            CP_COMMIT();
        }

        const uint32_t khb = cur;
        const uint32_t vhb = cur + (uint32_t)(MATH * 2);

        // ---- S = Q K^T : single pass, 16 rows x 128 keys in registers ----
        float sacc[16][4];
#pragma unroll
        for (int nf = 0; nf < 16; nf++)
#pragma unroll
            for (int c = 0; c < 4; c++) sacc[nf][c] = 0.f;

#pragma unroll
        for (int ks = 0; ks < 4; ks++) {
#pragma unroll
            for (int nfp = 0; nfp < 8; nfp++) {
                uint32_t off = (uint32_t)((nfp * 16 * KVS + ks * 16) * 2);
                uint32_t bh0, bh1, bh2, bh3;
                ldsm4(bh0, bh1, bh2, bh3, khb + off + kmofs);
                mma16816(sacc[2 * nfp],     qhf[ks], bh0, bh1);
                mma16816(sacc[2 * nfp + 1], qhf[ks], bh2, bh3);
            }
        }

        // ---- softmax in registers (rows g and g+8 of this warp's 16) ----
        float mx_a = sacc[0][0], mx_b = sacc[0][2];
#pragma unroll
        for (int nf = 0; nf < 16; nf++) {
            mx_a = fmaxf(mx_a, fmaxf(sacc[nf][0], sacc[nf][1]));
            mx_b = fmaxf(mx_b, fmaxf(sacc[nf][2], sacc[nf][3]));
        }
        mx_a = fmaxf(mx_a, __shfl_xor_sync(0xffffffffu, mx_a, 1));
        mx_a = fmaxf(mx_a, __shfl_xor_sync(0xffffffffu, mx_a, 2));
        mx_b = fmaxf(mx_b, __shfl_xor_sync(0xffffffffu, mx_b, 1));
        mx_b = fmaxf(mx_b, __shfl_xor_sync(0xffffffffu, mx_b, 2));
        float sum_a = 0.f, sum_b = 0.f;
#pragma unroll
        for (int nf = 0; nf < 16; nf++) {
            sacc[nf][0] = __expf(sacc[nf][0] - mx_a);
            sacc[nf][1] = __expf(sacc[nf][1] - mx_a);
            sacc[nf][2] = __expf(sacc[nf][2] - mx_b);
            sacc[nf][3] = __expf(sacc[nf][3] - mx_b);
            sum_a += sacc[nf][0] + sacc[nf][1];
            sum_b += sacc[nf][2] + sacc[nf][3];
        }
        sum_a += __shfl_xor_sync(0xffffffffu, sum_a, 1);
        sum_a += __shfl_xor_sync(0xffffffffu, sum_a, 2);
        sum_b += __shfl_xor_sync(0xffffffffu, sum_b, 1);
        sum_b += __shfl_xor_sync(0xffffffffu, sum_b, 2);
        const float inv_a = 1.0f / sum_a, inv_b = 1.0f / sum_b;

        // ---- pack P into A-fragments (fp16) ----
        uint32_t pah[8][4];
#pragma unroll
        for (int s = 0; s < 8; s++) {
#pragma unroll
            for (int hf = 0; hf < 2; hf++) {
                int nf = 2 * s + hf;
                __half2 p01 = __floats2half2_rn(sacc[nf][0] * inv_a,
                                                sacc[nf][1] * inv_a);
                __half2 p23 = __floats2half2_rn(sacc[nf][2] * inv_b,
                                                sacc[nf][3] * inv_b);
                pah[s][2 * hf]     = *(uint32_t*)&p01;
                pah[s][2 * hf + 1] = *(uint32_t*)&p23;
            }
        }

        // ---- O += P V : single pass, V via ldmatrix.trans ----
#pragma unroll
        for (int s = 0; s < 8; s++) {
#pragma unroll
            for (int nfp = 0; nfp < 4; nfp++) {
                uint32_t off = (uint32_t)((s * 16 * KVS + nfp * 16) * 2);
                uint32_t bh0, bh1, bh2, bh3;
                ldsm4t(bh0, bh1, bh2, bh3, vhb + off + vmofs);
                mma16816(oacc[2 * nfp],     pah[s], bh0, bh1);
                mma16816(oacc[2 * nfp + 1], pah[s], bh2, bh3);
            }
        }
    }

    // ---- write O ----
#pragma unroll
    for (int nf = 0; nf < 8; nf++) {
        size_t r0 = (size_t)(qrow + w * 16 + g) * HS + nf * 8 + 2 * tg;
        size_t r1 = (size_t)(qrow + w * 16 + g + 8) * HS + nf * 8 + 2 * tg;
        *(float2*)&out[r0] = make_float2(oacc[nf][0], oacc[nf][1]);
        *(float2*)&out[r1] = make_float2(oacc[nf][2], oacc[nf][3]);
    }
}

// ---------------------------------------------------------------------------
extern "C" void kernel_launch(void* const* d_in, const int* in_sizes, int n_in,
                              void* d_out, int out_size)
{
    const float* x  = (const float*)d_in[0];
    const float* Wq = (const float*)d_in[1];
    const float* Wk = (const float*)d_in[2];
    const float* Wv = (const float*)d_in[3];
    float* out = (float*)d_out;

    wsplit_kernel<<<192, 256>>>(Wq, Wk, Wv);

    int qsmemB = (64 * QXS + 2 * 192 * QWS) * (int)sizeof(__half);  // 35840
    cudaFuncSetAttribute(qkv_kernel, cudaFuncAttributeMaxDynamicSharedMemorySize, qsmemB);
    qkv_kernel<<<1024, 128, qsmemB>>>(x);

    int asmemB = 2 * BUFH * (int)sizeof(__half);   // 73728
    cudaFuncSetAttribute(attn_kernel, cudaFuncAttributeMaxDynamicSharedMemorySize, asmemB);
    attn_kernel<<<1024, 128, asmemB>>>(out);
}